// round 11
// baseline (speedup 1.0000x reference)
#include <cuda_runtime.h>
#include <cuda_bf16.h>
#include <cstdint>

#define N_NODES 50000
#define N_EDGES 800000
#define D_IN    256
#define D_OUT   128
#define EPSV    1e-9f

// Scratch (allocation-free rule: __device__ globals)
__device__ float g_Z [(size_t)N_NODES * D_OUT];   // Z = feat @ W1   [N, 128]
__device__ float g_H1[(size_t)N_NODES * D_OUT];   // H1 = A @ Z      [N, 128]
// W pre-transposed to [n][k] and bf16-split: B[n][k] = W[k][n] (n<128 -> W0, else W1)
__device__ __nv_bfloat16 g_Whi[256 * 256];
__device__ __nv_bfloat16 g_Wlo[256 * 256];

__device__ __forceinline__ uint32_t smem_u32(const void* p) {
    uint32_t a;
    asm("{ .reg .u64 t; cvta.to.shared.u64 t, %1; cvt.u32.u64 %0, t; }" : "=r"(a) : "l"(p));
    return a;
}

// ---------------- W split kernel: g_W{hi,lo}[n][k] = split(W[k][n]) ----------------
__global__ void splitw_kernel(const float* __restrict__ W0, const float* __restrict__ W1) {
    int id = blockIdx.x * 256 + threadIdx.x;   // 65536
    int n = id >> 8, k = id & 255;
    float w = (n < 128) ? __ldg(W0 + k * 128 + n) : __ldg(W1 + k * 128 + (n - 128));
    __nv_bfloat16 h = __float2bfloat16(w);
    float lo = w - __bfloat162float(h);
    g_Whi[n * 256 + k] = h;
    g_Wlo[n * 256 + k] = __float2bfloat16(lo);
}

// ---------------- zero H1 ----------------
__global__ void zero_h1_kernel() {
    int idx = blockIdx.x * blockDim.x + threadIdx.x;
    const int total = N_NODES * D_OUT / 4;
    if (idx < total)
        reinterpret_cast<float4*>(g_H1)[idx] = make_float4(0.f, 0.f, 0.f, 0.f);
}

// ---------------- HMMA GEMM + fused LN0 ------------------------------------------
// out[:, :128] = LN(relu(feat@W0 + b0));  g_Z = feat@W1 (raw)
// 512 threads = 16 warps, warp grid 2(M) x 8(N), warp tile 64x32.
// D = Ahi@Bhi + Ahi@Blo + Alo@Bhi via mma.sync.m16n8k16.bf16, fp32 acc in regs.
// K pipelined in chunks of 32 with double-buffered smem (cp.async for B).
#define MT   128
#define KCH  32
#define ASTR 40                          // bf16 row stride (80B = 5x16B, ldmatrix conflict-free)
#define A_HI_OFF 0
#define A_LO_OFF (MT * ASTR * 2)                   // 10240
#define B_HI_OFF (A_LO_OFF + MT * ASTR * 2)        // 20480
#define B_LO_OFF (B_HI_OFF + 256 * ASTR * 2)       // 40960
#define SSTR     (B_LO_OFF + 256 * ASTR * 2)       // 61440 per stage
#define HMMA_SMEM (2 * SSTR)                        // 122880 B

__device__ __forceinline__ void ldm_x4(uint32_t* r, uint32_t addr) {
    asm volatile("ldmatrix.sync.aligned.m8n8.x4.shared.b16 {%0,%1,%2,%3}, [%4];"
                 : "=r"(r[0]), "=r"(r[1]), "=r"(r[2]), "=r"(r[3]) : "r"(addr));
}
__device__ __forceinline__ void ldm_x2(uint32_t* r, uint32_t addr) {
    asm volatile("ldmatrix.sync.aligned.m8n8.x2.shared.b16 {%0,%1}, [%2];"
                 : "=r"(r[0]), "=r"(r[1]) : "r"(addr));
}
__device__ __forceinline__ void mma_bf16(float* c, const uint32_t* a, const uint32_t* b) {
    asm volatile("mma.sync.aligned.m16n8k16.row.col.f32.bf16.bf16.f32 "
                 "{%0,%1,%2,%3}, {%4,%5,%6,%7}, {%8,%9}, {%0,%1,%2,%3};"
                 : "+f"(c[0]), "+f"(c[1]), "+f"(c[2]), "+f"(c[3])
                 : "r"(a[0]), "r"(a[1]), "r"(a[2]), "r"(a[3]), "r"(b[0]), "r"(b[1]));
}
__device__ __forceinline__ void cp16(uint32_t dst, const void* src) {
    asm volatile("cp.async.cg.shared.global [%0], [%1], 16;" :: "r"(dst), "l"(src));
}
#define CP_COMMIT() asm volatile("cp.async.commit_group;" ::: "memory")
#define CP_WAIT0()  asm volatile("cp.async.wait_group 0;" ::: "memory")

__device__ __forceinline__ unsigned long long pack_bf16x4(float a, float b, float c, float d) {
    __nv_bfloat16 h0 = __float2bfloat16(a), h1 = __float2bfloat16(b);
    __nv_bfloat16 h2 = __float2bfloat16(c), h3 = __float2bfloat16(d);
    return (unsigned long long)__bfloat16_as_ushort(h0)
         | ((unsigned long long)__bfloat16_as_ushort(h1) << 16)
         | ((unsigned long long)__bfloat16_as_ushort(h2) << 32)
         | ((unsigned long long)__bfloat16_as_ushort(h3) << 48);
}

__global__ void __launch_bounds__(512, 1)
gemm_hmma_kernel(const float* __restrict__ feat,
                 const float* __restrict__ b0, const float* __restrict__ scale0,
                 const float* __restrict__ offset0, float* __restrict__ out)
{
    extern __shared__ char smem[];
    const uint32_t sb = smem_u32(smem);
    const int tid  = threadIdx.x;
    const int warp = tid >> 5;
    const int lane = tid & 31;
    const int mw   = warp >> 3;   // 0..1
    const int nw   = warp & 7;    // 0..7
    const int row0 = blockIdx.x * MT;

    // loader coords: A: thread -> row tid>>2, cols (tid&3)*8..+7
    const int a_lrow = tid >> 2;
    const int a_lcol = (tid & 3) * 8;
    const int a_grow = row0 + a_lrow;

    float acc[4][4][4];
#pragma unroll
    for (int mi = 0; mi < 4; ++mi)
#pragma unroll
        for (int ni = 0; ni < 4; ++ni)
#pragma unroll
            for (int j = 0; j < 4; ++j) acc[mi][ni][j] = 0.f;

    // ldmatrix lane-address components
    const int a_row  = mw * 64 + (lane & 15);
    const int a_coff = (lane >> 4) * 8;
    const int b_row  = nw * 32 + (lane & 7);
    const int b_koff = ((lane >> 3) & 1) * 8;

    float8_t: ;
    float ar[8];

    // ---- helpers as lambdas ----
    auto issue_B = [&](int kc, uint32_t stoff) {
#pragma unroll
        for (int j = 0; j < 2; ++j) {
            int idx = tid + j * 512;           // 0..1023
            int n = idx >> 2, ch = idx & 3;
            uint32_t doff = (uint32_t)(n * ASTR + ch * 8) * 2;
            cp16(sb + stoff + B_HI_OFF + doff, g_Whi + n * 256 + kc * KCH + ch * 8);
            cp16(sb + stoff + B_LO_OFF + doff, g_Wlo + n * 256 + kc * KCH + ch * 8);
        }
        CP_COMMIT();
    };
    auto issue_A = [&](int kc) {
        float4 v0 = make_float4(0.f, 0.f, 0.f, 0.f), v1 = v0;
        if (a_grow < N_NODES) {
            v0 = *reinterpret_cast<const float4*>(feat + (size_t)a_grow * D_IN + kc * KCH + a_lcol);
            v1 = *reinterpret_cast<const float4*>(feat + (size_t)a_grow * D_IN + kc * KCH + a_lcol + 4);
        }
        ar[0] = v0.x; ar[1] = v0.y; ar[2] = v0.z; ar[3] = v0.w;
        ar[4] = v1.x; ar[5] = v1.y; ar[6] = v1.z; ar[7] = v1.w;
    };
    auto store_A = [&](uint32_t stoff) {
        unsigned long long h0 = pack_bf16x4(ar[0], ar[1], ar[2], ar[3]);
        unsigned long long h1 = pack_bf16x4(ar[4], ar[5], ar[6], ar[7]);
        float l[8];
#pragma unroll
        for (int j = 0; j < 8; ++j) {
            __nv_bfloat16 h = __float2bfloat16(ar[j]);
            l[j] = ar[j] - __bfloat162float(h);
        }
        unsigned long long lo0 = pack_bf16x4(l[0], l[1], l[2], l[3]);
        unsigned long long lo1 = pack_bf16x4(l[4], l[5], l[6], l[7]);
        size_t off = ((size_t)a_lrow * ASTR + a_lcol) * 2;
        *reinterpret_cast<unsigned long long*>(smem + stoff + A_HI_OFF + off) = h0;
        *reinterpret_cast<unsigned long long*>(smem + stoff + A_HI_OFF + off + 8) = h1;
        *reinterpret_cast<unsigned long long*>(smem + stoff + A_LO_OFF + off) = lo0;
        *reinterpret_cast<unsigned long long*>(smem + stoff + A_LO_OFF + off + 8) = lo1;
    };

    // ---- prologue: stage 0 ----
    issue_B(0, 0);
    issue_A(0);
    store_A(0);
    CP_WAIT0();
    __syncthreads();

    // ---- pipelined mainloop: 8 chunks of K=32 ----
    for (int kc = 0; kc < 8; ++kc) {
        const uint32_t cur = (kc & 1) ? SSTR : 0;
        const uint32_t nxt = (kc & 1) ? 0 : SSTR;
        if (kc < 7) { issue_B(kc + 1, nxt); issue_A(kc + 1); }

#pragma unroll
        for (int kk = 0; kk < 2; ++kk) {
            uint32_t a_hi[4][4], a_lo[4][4], b[4][2];
            uint32_t acol = kk * 16 + a_coff;
            uint32_t bcol = kk * 16 + b_koff;
#pragma unroll
            for (int mi = 0; mi < 4; ++mi)
                ldm_x4(a_hi[mi], sb + cur + A_HI_OFF + (uint32_t)((a_row + mi * 16) * ASTR + acol) * 2);
#pragma unroll
            for (int ni = 0; ni < 4; ++ni)
                ldm_x2(b[ni], sb + cur + B_HI_OFF + (uint32_t)((b_row + ni * 8) * ASTR + bcol) * 2);
#pragma unroll
            for (int mi = 0; mi < 4; ++mi)
#pragma unroll
                for (int ni = 0; ni < 4; ++ni) mma_bf16(acc[mi][ni], a_hi[mi], b[ni]);
#pragma unroll
            for (int mi = 0; mi < 4; ++mi)
                ldm_x4(a_lo[mi], sb + cur + A_LO_OFF + (uint32_t)((a_row + mi * 16) * ASTR + acol) * 2);
#pragma unroll
            for (int mi = 0; mi < 4; ++mi)
#pragma unroll
                for (int ni = 0; ni < 4; ++ni) mma_bf16(acc[mi][ni], a_lo[mi], b[ni]);
#pragma unroll
            for (int ni = 0; ni < 4; ++ni)
                ldm_x2(b[ni], sb + cur + B_LO_OFF + (uint32_t)((b_row + ni * 8) * ASTR + bcol) * 2);
#pragma unroll
            for (int mi = 0; mi < 4; ++mi)
#pragma unroll
                for (int ni = 0; ni < 4; ++ni) mma_bf16(acc[mi][ni], a_hi[mi], b[ni]);
        }

        if (kc < 7) { store_A(nxt); CP_WAIT0(); }
        __syncthreads();
    }

    // ---- fused epilogue ----
    // f0 warps (nw<4): LN(relu(D + b0)) -> out[:, :128]; Z warps (nw>=4): raw -> g_Z.
    float2* red = reinterpret_cast<float2*>(smem);     // [128] (s, q) per local row
    if (tid < 128) red[tid] = make_float2(0.f, 0.f);
    __syncthreads();

    const int rloc  = mw * 64 + (lane >> 2);           // + mi*16 (+8)
    const int cbase = (nw & 3) * 32 + 2 * (lane & 3);

    if (nw < 4) {
        // bias + relu in-place on acc, accumulate partial (s, q) per row
#pragma unroll
        for (int mi = 0; mi < 4; ++mi) {
            float s0 = 0.f, q0 = 0.f, s1 = 0.f, q1 = 0.f;
#pragma unroll
            for (int ni = 0; ni < 4; ++ni) {
                int col = cbase + ni * 8;
                float bx = __ldg(b0 + col), by = __ldg(b0 + col + 1);
                float v0 = fmaxf(acc[mi][ni][0] + bx, 0.f);
                float v1 = fmaxf(acc[mi][ni][1] + by, 0.f);
                float v2 = fmaxf(acc[mi][ni][2] + bx, 0.f);
                float v3 = fmaxf(acc[mi][ni][3] + by, 0.f);
                acc[mi][ni][0] = v0; acc[mi][ni][1] = v1;
                acc[mi][ni][2] = v2; acc[mi][ni][3] = v3;
                s0 += v0 + v1; q0 += v0 * v0 + v1 * v1;
                s1 += v2 + v3; q1 += v2 * v2 + v3 * v3;
            }
            // reduce over the 4 lanes of the quad (same row, different cols)
#pragma unroll
            for (int off = 1; off < 4; off <<= 1) {
                s0 += __shfl_xor_sync(0xffffffffu, s0, off);
                q0 += __shfl_xor_sync(0xffffffffu, q0, off);
                s1 += __shfl_xor_sync(0xffffffffu, s1, off);
                q1 += __shfl_xor_sync(0xffffffffu, q1, off);
            }
            if ((lane & 3) == 0) {
                atomicAdd(&red[rloc + mi * 16].x, s0);
                atomicAdd(&red[rloc + mi * 16].y, q0);
                atomicAdd(&red[rloc + mi * 16 + 8].x, s1);
                atomicAdd(&red[rloc + mi * 16 + 8].y, q1);
            }
        }
    } else {
        // Z path: raw D -> g_Z
#pragma unroll
        for (int mi = 0; mi < 4; ++mi) {
            int r0 = row0 + rloc + mi * 16;
            int r1 = r0 + 8;
#pragma unroll
            for (int ni = 0; ni < 4; ++ni) {
                int col = cbase + ni * 8;
                if (r0 < N_NODES)
                    *reinterpret_cast<float2*>(g_Z + (size_t)r0 * 128 + col) =
                        make_float2(acc[mi][ni][0], acc[mi][ni][1]);
                if (r1 < N_NODES)
                    *reinterpret_cast<float2*>(g_Z + (size_t)r1 * 128 + col) =
                        make_float2(acc[mi][ni][2], acc[mi][ni][3]);
            }
        }
    }
    __syncthreads();

    if (nw < 4) {
#pragma unroll
        for (int mi = 0; mi < 4; ++mi) {
            int l0 = rloc + mi * 16, l1 = l0 + 8;
            int r0 = row0 + l0, r1 = row0 + l1;
            float2 sq0 = red[l0], sq1 = red[l1];
            float m0 = sq0.x * (1.f / 128.f);
            float i0 = rsqrtf(sq0.y * (1.f / 128.f) - m0 * m0 + EPSV);
            float m1 = sq1.x * (1.f / 128.f);
            float i1 = rsqrtf(sq1.y * (1.f / 128.f) - m1 * m1 + EPSV);
#pragma unroll
            for (int ni = 0; ni < 4; ++ni) {
                int col = cbase + ni * 8;
                float sx = __ldg(scale0 + col), sy = __ldg(scale0 + col + 1);
                float ox = __ldg(offset0 + col), oy = __ldg(offset0 + col + 1);
                if (r0 < N_NODES)
                    *reinterpret_cast<float2*>(out + (size_t)r0 * 256 + col) =
                        make_float2((acc[mi][ni][0] - m0) * i0 * sx + ox,
                                    (acc[mi][ni][1] - m0) * i0 * sy + oy);
                if (r1 < N_NODES)
                    *reinterpret_cast<float2*>(out + (size_t)r1 * 256 + col) =
                        make_float2((acc[mi][ni][2] - m1) * i1 * sx + ox,
                                    (acc[mi][ni][3] - m1) * i1 * sy + oy);
            }
        }
    }
}

// ---------------- SpMM: H1[r] += val * Z[c], one warp per edge, D=128 ----------------
__global__ void __launch_bounds__(256)
spmm_kernel(const int* __restrict__ erow, const int* __restrict__ ecol,
            const float* __restrict__ eval)
{
    int e = blockIdx.x * 8 + (threadIdx.x >> 5);
    if (e >= N_EDGES) return;
    int lane = threadIdx.x & 31;
    int r = __ldg(erow + e);
    int c = __ldg(ecol + e);
    float v = __ldg(eval + e);
    float4 z = *reinterpret_cast<const float4*>(g_Z + (size_t)c * 128 + lane * 4);
    float* dst = g_H1 + (size_t)r * 128 + lane * 4;
    asm volatile("red.global.add.v4.f32 [%0], {%1, %2, %3, %4};"
                 :: "l"(dst), "f"(v * z.x), "f"(v * z.y), "f"(v * z.z), "f"(v * z.w) : "memory");
}

// ---------------- f1 epilogue: out[:, 128:] = LN(relu(H1 + b1)) ----------------
__global__ void __launch_bounds__(256)
ln1_kernel(const float* __restrict__ b1, const float* __restrict__ scale1,
           const float* __restrict__ offset1, float* __restrict__ out)
{
    int row = blockIdx.x * 8 + (threadIdx.x >> 5);
    if (row >= N_NODES) return;
    int lane = threadIdx.x & 31;
    float4 h = *reinterpret_cast<const float4*>(g_H1 + (size_t)row * 128 + lane * 4);
    float4 b = *reinterpret_cast<const float4*>(b1 + lane * 4);
    h.x = fmaxf(h.x + b.x, 0.f);
    h.y = fmaxf(h.y + b.y, 0.f);
    h.z = fmaxf(h.z + b.z, 0.f);
    h.w = fmaxf(h.w + b.w, 0.f);
    float s = h.x + h.y + h.z + h.w;
    float q = h.x * h.x + h.y * h.y + h.z * h.z + h.w * h.w;
#pragma unroll
    for (int off = 16; off > 0; off >>= 1) {
        s += __shfl_xor_sync(0xffffffffu, s, off);
        q += __shfl_xor_sync(0xffffffffu, q, off);
    }
    float mean = s * (1.f / 128.f);
    float var  = q * (1.f / 128.f) - mean * mean;
    float inv  = rsqrtf(var + EPSV);
    float4 sc = *reinterpret_cast<const float4*>(scale1 + lane * 4);
    float4 of = *reinterpret_cast<const float4*>(offset1 + lane * 4);
    float4 w;
    w.x = (h.x - mean) * inv * sc.x + of.x;
    w.y = (h.y - mean) * inv * sc.y + of.y;
    w.z = (h.z - mean) * inv * sc.z + of.z;
    w.w = (h.w - mean) * inv * sc.w + of.w;
    *reinterpret_cast<float4*>(out + (size_t)row * 256 + 128 + lane * 4) = w;
}

extern "C" void kernel_launch(void* const* d_in, const int* in_sizes, int n_in,
                              void* d_out, int out_size)
{
    const float* feat    = (const float*)d_in[0];
    const float* W0      = (const float*)d_in[1];
    const float* b0      = (const float*)d_in[2];
    const float* scale0  = (const float*)d_in[3];
    const float* offset0 = (const float*)d_in[4];
    const float* W1      = (const float*)d_in[5];
    const float* b1      = (const float*)d_in[6];
    const float* scale1  = (const float*)d_in[7];
    const float* offset1 = (const float*)d_in[8];
    const int*   erow    = (const int*)d_in[9];
    const int*   ecol    = (const int*)d_in[10];
    const float* eval    = (const float*)d_in[11];
    float* out = (float*)d_out;

    cudaFuncSetAttribute(gemm_hmma_kernel,
                         cudaFuncAttributeMaxDynamicSharedMemorySize, HMMA_SMEM);

    splitw_kernel<<<256, 256>>>(W0, W1);
    zero_h1_kernel<<<(N_NODES * D_OUT / 4 + 255) / 256, 256>>>();
    gemm_hmma_kernel<<<(N_NODES + MT - 1) / MT, 512, HMMA_SMEM>>>(
        feat, b0, scale0, offset0, out);
    spmm_kernel<<<(N_EDGES + 7) / 8, 256>>>(erow, ecol, eval);
    ln1_kernel<<<(N_NODES + 7) / 8, 256>>>(b1, scale1, offset1, out);
}

// round 12
// speedup vs baseline: 1.3537x; 1.3537x over previous
#include <cuda_runtime.h>
#include <cuda_bf16.h>
#include <cstdint>

#define N_NODES 50000
#define N_EDGES 800000
#define D_IN    256
#define D_OUT   128
#define EPSV    1e-9f

// Scratch (allocation-free rule: __device__ globals)
__device__ float g_Z [(size_t)N_NODES * D_OUT];   // Z = feat @ W1   [N, 128]
__device__ float g_H1[(size_t)N_NODES * D_OUT];   // H1 = A @ Z      [N, 128]
// W pre-transposed to [n][k] and bf16-split: B[n][k] = W[k][n] (n<128 -> W0, else W1)
__device__ __nv_bfloat16 g_Whi[256 * 256];
__device__ __nv_bfloat16 g_Wlo[256 * 256];

__device__ __forceinline__ uint32_t smem_u32(const void* p) {
    uint32_t a;
    asm("{ .reg .u64 t; cvta.to.shared.u64 t, %1; cvt.u32.u64 %0, t; }" : "=r"(a) : "l"(p));
    return a;
}

// ---------------- W split kernel: g_W{hi,lo}[n][k] = split(W[k][n]) ----------------
__global__ void splitw_kernel(const float* __restrict__ W0, const float* __restrict__ W1) {
    int id = blockIdx.x * 256 + threadIdx.x;   // 65536
    int n = id >> 8, k = id & 255;
    float w = (n < 128) ? __ldg(W0 + k * 128 + n) : __ldg(W1 + k * 128 + (n - 128));
    __nv_bfloat16 h = __float2bfloat16(w);
    float lo = w - __bfloat162float(h);
    g_Whi[n * 256 + k] = h;
    g_Wlo[n * 256 + k] = __float2bfloat16(lo);
}

// ---------------- zero H1 ----------------
__global__ void zero_h1_kernel() {
    int idx = blockIdx.x * blockDim.x + threadIdx.x;
    const int total = N_NODES * D_OUT / 4;
    if (idx < total)
        reinterpret_cast<float4*>(g_H1)[idx] = make_float4(0.f, 0.f, 0.f, 0.f);
}

// ---------------- HMMA GEMM (R10 verbatim): out[:, :128] = feat@W0 raw; g_Z = feat@W1 ----
#define MT   128
#define KCH  64
#define ASTR 72                         // bf16 row stride (144B = 9 x 16B, ldmatrix conflict-free)
#define A_HI_OFF 0
#define A_LO_OFF (MT * ASTR * 2)                 // 18432
#define B_HI_OFF (A_LO_OFF + MT * ASTR * 2)      // 36864
#define B_LO_OFF (B_HI_OFF + 256 * ASTR * 2)     // 73728
#define HMMA_SMEM (B_LO_OFF + 256 * ASTR * 2)    // 110592 B

__device__ __forceinline__ void ldm_x4(uint32_t* r, uint32_t addr) {
    asm volatile("ldmatrix.sync.aligned.m8n8.x4.shared.b16 {%0,%1,%2,%3}, [%4];"
                 : "=r"(r[0]), "=r"(r[1]), "=r"(r[2]), "=r"(r[3]) : "r"(addr));
}
__device__ __forceinline__ void ldm_x2(uint32_t* r, uint32_t addr) {
    asm volatile("ldmatrix.sync.aligned.m8n8.x2.shared.b16 {%0,%1}, [%2];"
                 : "=r"(r[0]), "=r"(r[1]) : "r"(addr));
}
__device__ __forceinline__ void mma_bf16(float* c, const uint32_t* a, const uint32_t* b) {
    asm volatile("mma.sync.aligned.m16n8k16.row.col.f32.bf16.bf16.f32 "
                 "{%0,%1,%2,%3}, {%4,%5,%6,%7}, {%8,%9}, {%0,%1,%2,%3};"
                 : "+f"(c[0]), "+f"(c[1]), "+f"(c[2]), "+f"(c[3])
                 : "r"(a[0]), "r"(a[1]), "r"(a[2]), "r"(a[3]), "r"(b[0]), "r"(b[1]));
}

__global__ void __launch_bounds__(512, 1)
gemm_hmma_kernel(const float* __restrict__ feat, float* __restrict__ out)
{
    extern __shared__ char smem[];
    const uint32_t sb = smem_u32(smem);
    const int tid  = threadIdx.x;
    const int warp = tid >> 5;
    const int lane = tid & 31;
    const int mw   = warp >> 3;   // 0..1
    const int nw   = warp & 7;    // 0..7
    const int row0 = blockIdx.x * MT;

    float acc[4][4][4];
#pragma unroll
    for (int mi = 0; mi < 4; ++mi)
#pragma unroll
        for (int ni = 0; ni < 4; ++ni)
#pragma unroll
            for (int j = 0; j < 4; ++j) acc[mi][ni][j] = 0.f;

    const int a_row  = mw * 64 + (lane & 15);
    const int a_coff = (lane >> 4) * 8;
    const int b_row  = nw * 32 + (lane & 7);
    const int b_koff = ((lane >> 3) & 1) * 8;

    for (int kc = 0; kc < 4; ++kc) {
#pragma unroll
        for (int j = 0; j < 4; ++j) {
            int i = tid + j * 512;
            int r = i >> 4, c4 = (i & 15) * 4;
            int grow = row0 + r;
            float4 v = make_float4(0.f, 0.f, 0.f, 0.f);
            if (grow < N_NODES)
                v = *reinterpret_cast<const float4*>(feat + (size_t)grow * D_IN + kc * KCH + c4);
            __nv_bfloat16 h0 = __float2bfloat16(v.x), h1 = __float2bfloat16(v.y);
            __nv_bfloat16 h2 = __float2bfloat16(v.z), h3 = __float2bfloat16(v.w);
            __nv_bfloat16 l0 = __float2bfloat16(v.x - __bfloat162float(h0));
            __nv_bfloat16 l1 = __float2bfloat16(v.y - __bfloat162float(h1));
            __nv_bfloat16 l2 = __float2bfloat16(v.z - __bfloat162float(h2));
            __nv_bfloat16 l3 = __float2bfloat16(v.w - __bfloat162float(h3));
            unsigned long long ph =
                (unsigned long long)__bfloat16_as_ushort(h0)
              | ((unsigned long long)__bfloat16_as_ushort(h1) << 16)
              | ((unsigned long long)__bfloat16_as_ushort(h2) << 32)
              | ((unsigned long long)__bfloat16_as_ushort(h3) << 48);
            unsigned long long pl =
                (unsigned long long)__bfloat16_as_ushort(l0)
              | ((unsigned long long)__bfloat16_as_ushort(l1) << 16)
              | ((unsigned long long)__bfloat16_as_ushort(l2) << 32)
              | ((unsigned long long)__bfloat16_as_ushort(l3) << 48);
            size_t off = ((size_t)r * ASTR + c4) * 2;
            *reinterpret_cast<unsigned long long*>(smem + A_HI_OFF + off) = ph;
            *reinterpret_cast<unsigned long long*>(smem + A_LO_OFF + off) = pl;
        }
#pragma unroll
        for (int j = 0; j < 4; ++j) {
            int i = tid + j * 512;
            int n = i >> 3, ch = i & 7;
            size_t off = ((size_t)n * ASTR + ch * 8) * 2;
            *reinterpret_cast<uint4*>(smem + B_HI_OFF + off) =
                *reinterpret_cast<const uint4*>(g_Whi + n * 256 + kc * KCH + ch * 8);
            *reinterpret_cast<uint4*>(smem + B_LO_OFF + off) =
                *reinterpret_cast<const uint4*>(g_Wlo + n * 256 + kc * KCH + ch * 8);
        }
        __syncthreads();

#pragma unroll
        for (int kk = 0; kk < 4; ++kk) {
            uint32_t a_hi[4][4], a_lo[4][4], b[4][2];
            uint32_t acol = kk * 16 + a_coff;
            uint32_t bcol = kk * 16 + b_koff;
#pragma unroll
            for (int mi = 0; mi < 4; ++mi)
                ldm_x4(a_hi[mi], sb + A_HI_OFF + ((a_row + mi * 16) * ASTR + acol) * 2);
#pragma unroll
            for (int ni = 0; ni < 4; ++ni)
                ldm_x2(b[ni], sb + B_HI_OFF + ((b_row + ni * 8) * ASTR + bcol) * 2);
#pragma unroll
            for (int mi = 0; mi < 4; ++mi)
#pragma unroll
                for (int ni = 0; ni < 4; ++ni) mma_bf16(acc[mi][ni], a_hi[mi], b[ni]);
#pragma unroll
            for (int mi = 0; mi < 4; ++mi)
                ldm_x4(a_lo[mi], sb + A_LO_OFF + ((a_row + mi * 16) * ASTR + acol) * 2);
#pragma unroll
            for (int mi = 0; mi < 4; ++mi)
#pragma unroll
                for (int ni = 0; ni < 4; ++ni) mma_bf16(acc[mi][ni], a_lo[mi], b[ni]);
#pragma unroll
            for (int ni = 0; ni < 4; ++ni)
                ldm_x2(b[ni], sb + B_LO_OFF + ((b_row + ni * 8) * ASTR + bcol) * 2);
#pragma unroll
            for (int mi = 0; mi < 4; ++mi)
#pragma unroll
                for (int ni = 0; ni < 4; ++ni) mma_bf16(acc[mi][ni], a_hi[mi], b[ni]);
        }
        __syncthreads();
    }

    const int rbase = row0 + mw * 64 + (lane >> 2);
    const int cbase = (nw & 3) * 32 + 2 * (lane & 3);
#pragma unroll
    for (int mi = 0; mi < 4; ++mi) {
        int r0 = rbase + mi * 16;
        int r1 = r0 + 8;
#pragma unroll
        for (int ni = 0; ni < 4; ++ni) {
            int col = cbase + ni * 8;
            float2 v0 = make_float2(acc[mi][ni][0], acc[mi][ni][1]);
            float2 v1 = make_float2(acc[mi][ni][2], acc[mi][ni][3]);
            if (nw < 4) {
                if (r0 < N_NODES) *reinterpret_cast<float2*>(out + (size_t)r0 * 256 + col) = v0;
                if (r1 < N_NODES) *reinterpret_cast<float2*>(out + (size_t)r1 * 256 + col) = v1;
            } else {
                if (r0 < N_NODES) *reinterpret_cast<float2*>(g_Z + (size_t)r0 * 128 + col) = v0;
                if (r1 < N_NODES) *reinterpret_cast<float2*>(g_Z + (size_t)r1 * 128 + col) = v1;
            }
        }
    }
}

// ---------------- ln0: in-place LN(relu(. + b0)) on out[:, :128] ----------------
__global__ void __launch_bounds__(256)
ln0_kernel(const float* __restrict__ b0, const float* __restrict__ scale0,
           const float* __restrict__ offset0, float* __restrict__ out)
{
    int row = blockIdx.x * 8 + (threadIdx.x >> 5);
    if (row >= N_NODES) return;
    int lane = threadIdx.x & 31;
    float4 h = *reinterpret_cast<const float4*>(out + (size_t)row * 256 + lane * 4);
    float4 b = *reinterpret_cast<const float4*>(b0 + lane * 4);
    h.x = fmaxf(h.x + b.x, 0.f);
    h.y = fmaxf(h.y + b.y, 0.f);
    h.z = fmaxf(h.z + b.z, 0.f);
    h.w = fmaxf(h.w + b.w, 0.f);
    float s = h.x + h.y + h.z + h.w;
    float q = h.x * h.x + h.y * h.y + h.z * h.z + h.w * h.w;
#pragma unroll
    for (int off = 16; off > 0; off >>= 1) {
        s += __shfl_xor_sync(0xffffffffu, s, off);
        q += __shfl_xor_sync(0xffffffffu, q, off);
    }
    float mean = s * (1.f / 128.f);
    float var  = q * (1.f / 128.f) - mean * mean;
    float inv  = rsqrtf(var + EPSV);
    float4 sc = *reinterpret_cast<const float4*>(scale0 + lane * 4);
    float4 of = *reinterpret_cast<const float4*>(offset0 + lane * 4);
    float4 w;
    w.x = (h.x - mean) * inv * sc.x + of.x;
    w.y = (h.y - mean) * inv * sc.y + of.y;
    w.z = (h.z - mean) * inv * sc.z + of.z;
    w.w = (h.w - mean) * inv * sc.w + of.w;
    *reinterpret_cast<float4*>(out + (size_t)row * 256 + lane * 4) = w;
}

// ---------------- SpMM: warp owns 32 edges; metadata via coalesced loads + shfl ------
// Per edge: 1 gather (4 wavefronts) + 1 RED (4 wavefronts); metadata amortized (3/32).
#define EPW 32
__global__ void __launch_bounds__(256)
spmm_kernel(const int* __restrict__ erow, const int* __restrict__ ecol,
            const float* __restrict__ eval)
{
    const int warp_id = blockIdx.x * 8 + (threadIdx.x >> 5);
    const int lane = threadIdx.x & 31;
    const int base = warp_id * EPW;
    if (base >= N_EDGES) return;

    // coalesced metadata load: lane's edge is base+lane (EPW==32)
    int   my_r = __ldg(erow + base + lane);
    int   my_c = __ldg(ecol + base + lane);
    float my_v = __ldg(eval + base + lane);

    const float* Zl  = g_Z  + lane * 4;
    float*       H1l = g_H1 + lane * 4;

#pragma unroll 4
    for (int j = 0; j < EPW; j += 2) {
        int   c0 = __shfl_sync(0xffffffffu, my_c, j);
        int   r0 = __shfl_sync(0xffffffffu, my_r, j);
        float v0 = __shfl_sync(0xffffffffu, my_v, j);
        int   c1 = __shfl_sync(0xffffffffu, my_c, j + 1);
        int   r1 = __shfl_sync(0xffffffffu, my_r, j + 1);
        float v1 = __shfl_sync(0xffffffffu, my_v, j + 1);
        float4 z0 = *reinterpret_cast<const float4*>(Zl + (size_t)c0 * 128);
        float4 z1 = *reinterpret_cast<const float4*>(Zl + (size_t)c1 * 128);
        float* d0 = H1l + (size_t)r0 * 128;
        float* d1 = H1l + (size_t)r1 * 128;
        asm volatile("red.global.add.v4.f32 [%0], {%1, %2, %3, %4};"
                     :: "l"(d0), "f"(v0 * z0.x), "f"(v0 * z0.y), "f"(v0 * z0.z), "f"(v0 * z0.w) : "memory");
        asm volatile("red.global.add.v4.f32 [%0], {%1, %2, %3, %4};"
                     :: "l"(d1), "f"(v1 * z1.x), "f"(v1 * z1.y), "f"(v1 * z1.z), "f"(v1 * z1.w) : "memory");
    }
}

// ---------------- f1 epilogue: out[:, 128:] = LN(relu(H1 + b1)) ----------------
__global__ void __launch_bounds__(256)
ln1_kernel(const float* __restrict__ b1, const float* __restrict__ scale1,
           const float* __restrict__ offset1, float* __restrict__ out)
{
    int row = blockIdx.x * 8 + (threadIdx.x >> 5);
    if (row >= N_NODES) return;
    int lane = threadIdx.x & 31;
    float4 h = *reinterpret_cast<const float4*>(g_H1 + (size_t)row * 128 + lane * 4);
    float4 b = *reinterpret_cast<const float4*>(b1 + lane * 4);
    h.x = fmaxf(h.x + b.x, 0.f);
    h.y = fmaxf(h.y + b.y, 0.f);
    h.z = fmaxf(h.z + b.z, 0.f);
    h.w = fmaxf(h.w + b.w, 0.f);
    float s = h.x + h.y + h.z + h.w;
    float q = h.x * h.x + h.y * h.y + h.z * h.z + h.w * h.w;
#pragma unroll
    for (int off = 16; off > 0; off >>= 1) {
        s += __shfl_xor_sync(0xffffffffu, s, off);
        q += __shfl_xor_sync(0xffffffffu, q, off);
    }
    float mean = s * (1.f / 128.f);
    float var  = q * (1.f / 128.f) - mean * mean;
    float inv  = rsqrtf(var + EPSV);
    float4 sc = *reinterpret_cast<const float4*>(scale1 + lane * 4);
    float4 of = *reinterpret_cast<const float4*>(offset1 + lane * 4);
    float4 w;
    w.x = (h.x - mean) * inv * sc.x + of.x;
    w.y = (h.y - mean) * inv * sc.y + of.y;
    w.z = (h.z - mean) * inv * sc.z + of.z;
    w.w = (h.w - mean) * inv * sc.w + of.w;
    *reinterpret_cast<float4*>(out + (size_t)row * 256 + 128 + lane * 4) = w;
}

extern "C" void kernel_launch(void* const* d_in, const int* in_sizes, int n_in,
                              void* d_out, int out_size)
{
    const float* feat    = (const float*)d_in[0];
    const float* W0      = (const float*)d_in[1];
    const float* b0      = (const float*)d_in[2];
    const float* scale0  = (const float*)d_in[3];
    const float* offset0 = (const float*)d_in[4];
    const float* W1      = (const float*)d_in[5];
    const float* b1      = (const float*)d_in[6];
    const float* scale1  = (const float*)d_in[7];
    const float* offset1 = (const float*)d_in[8];
    const int*   erow    = (const int*)d_in[9];
    const int*   ecol    = (const int*)d_in[10];
    const float* eval    = (const float*)d_in[11];
    float* out = (float*)d_out;

    cudaFuncSetAttribute(gemm_hmma_kernel,
                         cudaFuncAttributeMaxDynamicSharedMemorySize, HMMA_SMEM);

    splitw_kernel<<<256, 256>>>(W0, W1);
    zero_h1_kernel<<<(N_NODES * D_OUT / 4 + 255) / 256, 256>>>();
    gemm_hmma_kernel<<<(N_NODES + MT - 1) / MT, 512, HMMA_SMEM>>>(feat, out);
    ln0_kernel<<<(N_NODES + 7) / 8, 256>>>(b0, scale0, offset0, out);
    spmm_kernel<<<(N_EDGES / EPW + 7) / 8, 256>>>(erow, ecol, eval);
    ln1_kernel<<<(N_NODES + 7) / 8, 256>>>(b1, scale1, offset1, out);
}

// round 13
// speedup vs baseline: 1.4205x; 1.0494x over previous
#include <cuda_runtime.h>
#include <cuda_bf16.h>
#include <cstdint>

#define N_NODES 50000
#define N_EDGES 800000
#define D_IN    256
#define D_OUT   128
#define EPSV    1e-9f

// Scratch (allocation-free rule: __device__ globals)
__device__ float g_Z [(size_t)N_NODES * D_OUT];   // Z = feat @ W1   [N, 128]
__device__ float g_H1[(size_t)N_NODES * D_OUT];   // H1 = A @ Z      [N, 128]
// W pre-transposed to [n][k] and bf16-split: B[n][k] = W[k][n] (n<128 -> W0, else W1)
__device__ __nv_bfloat16 g_Whi[256 * 256];
__device__ __nv_bfloat16 g_Wlo[256 * 256];

__device__ __forceinline__ uint32_t smem_u32(const void* p) {
    uint32_t a;
    asm("{ .reg .u64 t; cvta.to.shared.u64 t, %1; cvt.u32.u64 %0, t; }" : "=r"(a) : "l"(p));
    return a;
}

// ---------------- prep: W split + zero H1 in one launch ----------------
// blocks [0, 256): W split (65536 elems); blocks [256, 6506): zero H1 (1.6M float4)
__global__ void prep_kernel(const float* __restrict__ W0, const float* __restrict__ W1) {
    int blk = blockIdx.x;
    if (blk < 256) {
        int id = blk * 256 + threadIdx.x;      // 65536
        int n = id >> 8, k = id & 255;
        float w = (n < 128) ? __ldg(W0 + k * 128 + n) : __ldg(W1 + k * 128 + (n - 128));
        __nv_bfloat16 h = __float2bfloat16(w);
        float lo = w - __bfloat162float(h);
        g_Whi[n * 256 + k] = h;
        g_Wlo[n * 256 + k] = __float2bfloat16(lo);
    } else {
        int idx = (blk - 256) * 256 + threadIdx.x;
        const int total = N_NODES * D_OUT / 4;
        if (idx < total)
            reinterpret_cast<float4*>(g_H1)[idx] = make_float4(0.f, 0.f, 0.f, 0.f);
    }
}

// ---------------- HMMA GEMM + fused LN0 ------------------------------------------
// out[:, :128] = LN(relu(feat@W0 + b0));  g_Z = feat@W1 (raw)
// Mainloop is R10-verbatim (known-good, no spills); only the epilogue is fused.
#define MT   128
#define KCH  64
#define ASTR 72                         // bf16 row stride (144B = 9 x 16B, ldmatrix conflict-free)
#define A_HI_OFF 0
#define A_LO_OFF (MT * ASTR * 2)                 // 18432
#define B_HI_OFF (A_LO_OFF + MT * ASTR * 2)      // 36864
#define B_LO_OFF (B_HI_OFF + 256 * ASTR * 2)     // 73728
#define HMMA_SMEM (B_LO_OFF + 256 * ASTR * 2)    // 110592 B

__device__ __forceinline__ void ldm_x4(uint32_t* r, uint32_t addr) {
    asm volatile("ldmatrix.sync.aligned.m8n8.x4.shared.b16 {%0,%1,%2,%3}, [%4];"
                 : "=r"(r[0]), "=r"(r[1]), "=r"(r[2]), "=r"(r[3]) : "r"(addr));
}
__device__ __forceinline__ void ldm_x2(uint32_t* r, uint32_t addr) {
    asm volatile("ldmatrix.sync.aligned.m8n8.x2.shared.b16 {%0,%1}, [%2];"
                 : "=r"(r[0]), "=r"(r[1]) : "r"(addr));
}
__device__ __forceinline__ void mma_bf16(float* c, const uint32_t* a, const uint32_t* b) {
    asm volatile("mma.sync.aligned.m16n8k16.row.col.f32.bf16.bf16.f32 "
                 "{%0,%1,%2,%3}, {%4,%5,%6,%7}, {%8,%9}, {%0,%1,%2,%3};"
                 : "+f"(c[0]), "+f"(c[1]), "+f"(c[2]), "+f"(c[3])
                 : "r"(a[0]), "r"(a[1]), "r"(a[2]), "r"(a[3]), "r"(b[0]), "r"(b[1]));
}

__global__ void __launch_bounds__(512, 1)
gemm_hmma_kernel(const float* __restrict__ feat,
                 const float* __restrict__ b0, const float* __restrict__ scale0,
                 const float* __restrict__ offset0, float* __restrict__ out)
{
    extern __shared__ char smem[];
    const uint32_t sb = smem_u32(smem);
    const int tid  = threadIdx.x;
    const int warp = tid >> 5;
    const int lane = tid & 31;
    const int mw   = warp >> 3;   // 0..1
    const int nw   = warp & 7;    // 0..7
    const int row0 = blockIdx.x * MT;

    float acc[4][4][4];
#pragma unroll
    for (int mi = 0; mi < 4; ++mi)
#pragma unroll
        for (int ni = 0; ni < 4; ++ni)
#pragma unroll
            for (int j = 0; j < 4; ++j) acc[mi][ni][j] = 0.f;

    const int a_row  = mw * 64 + (lane & 15);
    const int a_coff = (lane >> 4) * 8;
    const int b_row  = nw * 32 + (lane & 7);
    const int b_koff = ((lane >> 3) & 1) * 8;

    for (int kc = 0; kc < 4; ++kc) {
#pragma unroll
        for (int j = 0; j < 4; ++j) {
            int i = tid + j * 512;
            int r = i >> 4, c4 = (i & 15) * 4;
            int grow = row0 + r;
            float4 v = make_float4(0.f, 0.f, 0.f, 0.f);
            if (grow < N_NODES)
                v = *reinterpret_cast<const float4*>(feat + (size_t)grow * D_IN + kc * KCH + c4);
            __nv_bfloat16 h0 = __float2bfloat16(v.x), h1 = __float2bfloat16(v.y);
            __nv_bfloat16 h2 = __float2bfloat16(v.z), h3 = __float2bfloat16(v.w);
            __nv_bfloat16 l0 = __float2bfloat16(v.x - __bfloat162float(h0));
            __nv_bfloat16 l1 = __float2bfloat16(v.y - __bfloat162float(h1));
            __nv_bfloat16 l2 = __float2bfloat16(v.z - __bfloat162float(h2));
            __nv_bfloat16 l3 = __float2bfloat16(v.w - __bfloat162float(h3));
            unsigned long long ph =
                (unsigned long long)__bfloat16_as_ushort(h0)
              | ((unsigned long long)__bfloat16_as_ushort(h1) << 16)
              | ((unsigned long long)__bfloat16_as_ushort(h2) << 32)
              | ((unsigned long long)__bfloat16_as_ushort(h3) << 48);
            unsigned long long pl =
                (unsigned long long)__bfloat16_as_ushort(l0)
              | ((unsigned long long)__bfloat16_as_ushort(l1) << 16)
              | ((unsigned long long)__bfloat16_as_ushort(l2) << 32)
              | ((unsigned long long)__bfloat16_as_ushort(l3) << 48);
            size_t off = ((size_t)r * ASTR + c4) * 2;
            *reinterpret_cast<unsigned long long*>(smem + A_HI_OFF + off) = ph;
            *reinterpret_cast<unsigned long long*>(smem + A_LO_OFF + off) = pl;
        }
#pragma unroll
        for (int j = 0; j < 4; ++j) {
            int i = tid + j * 512;
            int n = i >> 3, ch = i & 7;
            size_t off = ((size_t)n * ASTR + ch * 8) * 2;
            *reinterpret_cast<uint4*>(smem + B_HI_OFF + off) =
                *reinterpret_cast<const uint4*>(g_Whi + n * 256 + kc * KCH + ch * 8);
            *reinterpret_cast<uint4*>(smem + B_LO_OFF + off) =
                *reinterpret_cast<const uint4*>(g_Wlo + n * 256 + kc * KCH + ch * 8);
        }
        __syncthreads();

#pragma unroll
        for (int kk = 0; kk < 4; ++kk) {
            uint32_t a_hi[4][4], a_lo[4][4], b[4][2];
            uint32_t acol = kk * 16 + a_coff;
            uint32_t bcol = kk * 16 + b_koff;
#pragma unroll
            for (int mi = 0; mi < 4; ++mi)
                ldm_x4(a_hi[mi], sb + A_HI_OFF + ((a_row + mi * 16) * ASTR + acol) * 2);
#pragma unroll
            for (int ni = 0; ni < 4; ++ni)
                ldm_x2(b[ni], sb + B_HI_OFF + ((b_row + ni * 8) * ASTR + bcol) * 2);
#pragma unroll
            for (int mi = 0; mi < 4; ++mi)
#pragma unroll
                for (int ni = 0; ni < 4; ++ni) mma_bf16(acc[mi][ni], a_hi[mi], b[ni]);
#pragma unroll
            for (int mi = 0; mi < 4; ++mi)
                ldm_x4(a_lo[mi], sb + A_LO_OFF + ((a_row + mi * 16) * ASTR + acol) * 2);
#pragma unroll
            for (int mi = 0; mi < 4; ++mi)
#pragma unroll
                for (int ni = 0; ni < 4; ++ni) mma_bf16(acc[mi][ni], a_lo[mi], b[ni]);
#pragma unroll
            for (int ni = 0; ni < 4; ++ni)
                ldm_x2(b[ni], sb + B_LO_OFF + ((b_row + ni * 8) * ASTR + bcol) * 2);
#pragma unroll
            for (int mi = 0; mi < 4; ++mi)
#pragma unroll
                for (int ni = 0; ni < 4; ++ni) mma_bf16(acc[mi][ni], a_hi[mi], b[ni]);
        }
        __syncthreads();
    }

    // ---- fused epilogue ----
    // f0 warps (nw<4): LN(relu(D + b0)) -> out[:, :128]; Z warps (nw>=4): raw -> g_Z.
    float2* red = reinterpret_cast<float2*>(smem);     // [128] (s, q) per local row
    if (tid < 128) red[tid] = make_float2(0.f, 0.f);
    __syncthreads();

    const int rloc  = mw * 64 + (lane >> 2);           // + mi*16 (+8)
    const int cbase = (nw & 3) * 32 + 2 * (lane & 3);

    if (nw < 4) {
        // bias + relu in-place on acc, accumulate partial (s, q) per row
#pragma unroll
        for (int mi = 0; mi < 4; ++mi) {
            float s0 = 0.f, q0 = 0.f, s1 = 0.f, q1 = 0.f;
#pragma unroll
            for (int ni = 0; ni < 4; ++ni) {
                int col = cbase + ni * 8;
                float bx = __ldg(b0 + col), by = __ldg(b0 + col + 1);
                float v0 = fmaxf(acc[mi][ni][0] + bx, 0.f);
                float v1 = fmaxf(acc[mi][ni][1] + by, 0.f);
                float v2 = fmaxf(acc[mi][ni][2] + bx, 0.f);
                float v3 = fmaxf(acc[mi][ni][3] + by, 0.f);
                acc[mi][ni][0] = v0; acc[mi][ni][1] = v1;
                acc[mi][ni][2] = v2; acc[mi][ni][3] = v3;
                s0 += v0 + v1; q0 += v0 * v0 + v1 * v1;
                s1 += v2 + v3; q1 += v2 * v2 + v3 * v3;
            }
            // reduce over the 4 lanes of the quad (same row, different cols)
#pragma unroll
            for (int off = 1; off < 4; off <<= 1) {
                s0 += __shfl_xor_sync(0xffffffffu, s0, off);
                q0 += __shfl_xor_sync(0xffffffffu, q0, off);
                s1 += __shfl_xor_sync(0xffffffffu, s1, off);
                q1 += __shfl_xor_sync(0xffffffffu, q1, off);
            }
            if ((lane & 3) == 0) {
                atomicAdd(&red[rloc + mi * 16].x, s0);
                atomicAdd(&red[rloc + mi * 16].y, q0);
                atomicAdd(&red[rloc + mi * 16 + 8].x, s1);
                atomicAdd(&red[rloc + mi * 16 + 8].y, q1);
            }
        }
    } else {
        // Z path: raw D -> g_Z
#pragma unroll
        for (int mi = 0; mi < 4; ++mi) {
            int r0 = row0 + rloc + mi * 16;
            int r1 = r0 + 8;
#pragma unroll
            for (int ni = 0; ni < 4; ++ni) {
                int col = cbase + ni * 8;
                if (r0 < N_NODES)
                    *reinterpret_cast<float2*>(g_Z + (size_t)r0 * 128 + col) =
                        make_float2(acc[mi][ni][0], acc[mi][ni][1]);
                if (r1 < N_NODES)
                    *reinterpret_cast<float2*>(g_Z + (size_t)r1 * 128 + col) =
                        make_float2(acc[mi][ni][2], acc[mi][ni][3]);
            }
        }
    }
    __syncthreads();

    if (nw < 4) {
#pragma unroll
        for (int mi = 0; mi < 4; ++mi) {
            int l0 = rloc + mi * 16, l1 = l0 + 8;
            int r0 = row0 + l0, r1 = row0 + l1;
            float2 sq0 = red[l0], sq1 = red[l1];
            float m0 = sq0.x * (1.f / 128.f);
            float i0 = rsqrtf(sq0.y * (1.f / 128.f) - m0 * m0 + EPSV);
            float m1 = sq1.x * (1.f / 128.f);
            float i1 = rsqrtf(sq1.y * (1.f / 128.f) - m1 * m1 + EPSV);
#pragma unroll
            for (int ni = 0; ni < 4; ++ni) {
                int col = cbase + ni * 8;
                float sx = __ldg(scale0 + col), sy = __ldg(scale0 + col + 1);
                float ox = __ldg(offset0 + col), oy = __ldg(offset0 + col + 1);
                if (r0 < N_NODES)
                    *reinterpret_cast<float2*>(out + (size_t)r0 * 256 + col) =
                        make_float2((acc[mi][ni][0] - m0) * i0 * sx + ox,
                                    (acc[mi][ni][1] - m0) * i0 * sy + oy);
                if (r1 < N_NODES)
                    *reinterpret_cast<float2*>(out + (size_t)r1 * 256 + col) =
                        make_float2((acc[mi][ni][2] - m1) * i1 * sx + ox,
                                    (acc[mi][ni][3] - m1) * i1 * sy + oy);
            }
        }
    }
}

// ---------------- SpMM: warp owns 32 edges; metadata via coalesced loads + shfl ------
#define EPW 32
__global__ void __launch_bounds__(256)
spmm_kernel(const int* __restrict__ erow, const int* __restrict__ ecol,
            const float* __restrict__ eval)
{
    const int warp_id = blockIdx.x * 8 + (threadIdx.x >> 5);
    const int lane = threadIdx.x & 31;
    const int base = warp_id * EPW;
    if (base >= N_EDGES) return;

    int   my_r = __ldg(erow + base + lane);
    int   my_c = __ldg(ecol + base + lane);
    float my_v = __ldg(eval + base + lane);

    const float* Zl  = g_Z  + lane * 4;
    float*       H1l = g_H1 + lane * 4;

#pragma unroll 2
    for (int j = 0; j < EPW; j += 4) {
        int   c0 = __shfl_sync(0xffffffffu, my_c, j);
        int   r0 = __shfl_sync(0xffffffffu, my_r, j);
        float v0 = __shfl_sync(0xffffffffu, my_v, j);
        int   c1 = __shfl_sync(0xffffffffu, my_c, j + 1);
        int   r1 = __shfl_sync(0xffffffffu, my_r, j + 1);
        float v1 = __shfl_sync(0xffffffffu, my_v, j + 1);
        int   c2 = __shfl_sync(0xffffffffu, my_c, j + 2);
        int   r2 = __shfl_sync(0xffffffffu, my_r, j + 2);
        float v2 = __shfl_sync(0xffffffffu, my_v, j + 2);
        int   c3 = __shfl_sync(0xffffffffu, my_c, j + 3);
        int   r3 = __shfl_sync(0xffffffffu, my_r, j + 3);
        float v3 = __shfl_sync(0xffffffffu, my_v, j + 3);
        float4 z0 = *reinterpret_cast<const float4*>(Zl + (size_t)c0 * 128);
        float4 z1 = *reinterpret_cast<const float4*>(Zl + (size_t)c1 * 128);
        float4 z2 = *reinterpret_cast<const float4*>(Zl + (size_t)c2 * 128);
        float4 z3 = *reinterpret_cast<const float4*>(Zl + (size_t)c3 * 128);
        asm volatile("red.global.add.v4.f32 [%0], {%1, %2, %3, %4};"
                     :: "l"(H1l + (size_t)r0 * 128), "f"(v0 * z0.x), "f"(v0 * z0.y), "f"(v0 * z0.z), "f"(v0 * z0.w) : "memory");
        asm volatile("red.global.add.v4.f32 [%0], {%1, %2, %3, %4};"
                     :: "l"(H1l + (size_t)r1 * 128), "f"(v1 * z1.x), "f"(v1 * z1.y), "f"(v1 * z1.z), "f"(v1 * z1.w) : "memory");
        asm volatile("red.global.add.v4.f32 [%0], {%1, %2, %3, %4};"
                     :: "l"(H1l + (size_t)r2 * 128), "f"(v2 * z2.x), "f"(v2 * z2.y), "f"(v2 * z2.z), "f"(v2 * z2.w) : "memory");
        asm volatile("red.global.add.v4.f32 [%0], {%1, %2, %3, %4};"
                     :: "l"(H1l + (size_t)r3 * 128), "f"(v3 * z3.x), "f"(v3 * z3.y), "f"(v3 * z3.z), "f"(v3 * z3.w) : "memory");
    }
}

// ---------------- f1 epilogue: out[:, 128:] = LN(relu(H1 + b1)) ----------------
__global__ void __launch_bounds__(256)
ln1_kernel(const float* __restrict__ b1, const float* __restrict__ scale1,
           const float* __restrict__ offset1, float* __restrict__ out)
{
    int row = blockIdx.x * 8 + (threadIdx.x >> 5);
    if (row >= N_NODES) return;
    int lane = threadIdx.x & 31;
    float4 h = *reinterpret_cast<const float4*>(g_H1 + (size_t)row * 128 + lane * 4);
    float4 b = *reinterpret_cast<const float4*>(b1 + lane * 4);
    h.x = fmaxf(h.x + b.x, 0.f);
    h.y = fmaxf(h.y + b.y, 0.f);
    h.z = fmaxf(h.z + b.z, 0.f);
    h.w = fmaxf(h.w + b.w, 0.f);
    float s = h.x + h.y + h.z + h.w;
    float q = h.x * h.x + h.y * h.y + h.z * h.z + h.w * h.w;
#pragma unroll
    for (int off = 16; off > 0; off >>= 1) {
        s += __shfl_xor_sync(0xffffffffu, s, off);
        q += __shfl_xor_sync(0xffffffffu, q, off);
    }
    float mean = s * (1.f / 128.f);
    float var  = q * (1.f / 128.f) - mean * mean;
    float inv  = rsqrtf(var + EPSV);
    float4 sc = *reinterpret_cast<const float4*>(scale1 + lane * 4);
    float4 of = *reinterpret_cast<const float4*>(offset1 + lane * 4);
    float4 w;
    w.x = (h.x - mean) * inv * sc.x + of.x;
    w.y = (h.y - mean) * inv * sc.y + of.y;
    w.z = (h.z - mean) * inv * sc.z + of.z;
    w.w = (h.w - mean) * inv * sc.w + of.w;
    *reinterpret_cast<float4*>(out + (size_t)row * 256 + 128 + lane * 4) = w;
}

extern "C" void kernel_launch(void* const* d_in, const int* in_sizes, int n_in,
                              void* d_out, int out_size)
{
    const float* feat    = (const float*)d_in[0];
    const float* W0      = (const float*)d_in[1];
    const float* b0      = (const float*)d_in[2];
    const float* scale0  = (const float*)d_in[3];
    const float* offset0 = (const float*)d_in[4];
    const float* W1      = (const float*)d_in[5];
    const float* b1      = (const float*)d_in[6];
    const float* scale1  = (const float*)d_in[7];
    const float* offset1 = (const float*)d_in[8];
    const int*   erow    = (const int*)d_in[9];
    const int*   ecol    = (const int*)d_in[10];
    const float* eval    = (const float*)d_in[11];
    float* out = (float*)d_out;

    cudaFuncSetAttribute(gemm_hmma_kernel,
                         cudaFuncAttributeMaxDynamicSharedMemorySize, HMMA_SMEM);

    prep_kernel<<<256 + (N_NODES * D_OUT / 4 + 255) / 256, 256>>>(W0, W1);
    gemm_hmma_kernel<<<(N_NODES + MT - 1) / MT, 512, HMMA_SMEM>>>(
        feat, b0, scale0, offset0, out);
    spmm_kernel<<<(N_EDGES / EPW + 7) / 8, 256>>>(erow, ecol, eval);
    ln1_kernel<<<(N_NODES + 7) / 8, 256>>>(b1, scale1, offset1, out);
}

// round 14
// speedup vs baseline: 1.4297x; 1.0065x over previous
#include <cuda_runtime.h>
#include <cuda_bf16.h>
#include <cstdint>

#define N_NODES 50000
#define N_EDGES 800000
#define D_IN    256
#define D_OUT   128
#define EPSV    1e-9f

// Scratch (allocation-free rule: __device__ globals)
__device__ float g_Z [(size_t)N_NODES * D_OUT];   // Z = feat @ W1   [N, 128]
__device__ float g_H1[(size_t)N_NODES * D_OUT];   // H1 = A @ Z      [N, 128]
// W pre-transposed to [n][k] and bf16-split: B[n][k] = W[k][n] (n<128 -> W0, else W1)
__device__ __nv_bfloat16 g_Whi[256 * 256];
__device__ __nv_bfloat16 g_Wlo[256 * 256];

__device__ __forceinline__ uint32_t smem_u32(const void* p) {
    uint32_t a;
    asm("{ .reg .u64 t; cvta.to.shared.u64 t, %1; cvt.u32.u64 %0, t; }" : "=r"(a) : "l"(p));
    return a;
}

// ---------------- prep: W split + zero H1 in one launch ----------------
__global__ void prep_kernel(const float* __restrict__ W0, const float* __restrict__ W1) {
    int blk = blockIdx.x;
    if (blk < 256) {
        int id = blk * 256 + threadIdx.x;      // 65536
        int n = id >> 8, k = id & 255;
        float w = (n < 128) ? __ldg(W0 + k * 128 + n) : __ldg(W1 + k * 128 + (n - 128));
        __nv_bfloat16 h = __float2bfloat16(w);
        float lo = w - __bfloat162float(h);
        g_Whi[n * 256 + k] = h;
        g_Wlo[n * 256 + k] = __float2bfloat16(lo);
    } else {
        int idx = (blk - 256) * 256 + threadIdx.x;
        const int total = N_NODES * D_OUT / 4;
        if (idx < total)
            reinterpret_cast<float4*>(g_H1)[idx] = make_float4(0.f, 0.f, 0.f, 0.f);
    }
}

// ---------------- HMMA GEMM, N-split for 2 CTAs/SM --------------------------------
// Block pair (tile, h): h=0 -> out[:, :128] = LN(relu(feat@W0+b0)); h=1 -> g_Z = feat@W1.
// CTA: 256 threads / 8 warps, warp grid 2(M) x 4(N), warp tile 64x32, tile M=128 N=128.
#define MT   128
#define KCH  64
#define ASTR 72                         // bf16 row stride (144B = 9 x 16B, ldmatrix conflict-free)
#define A_HI_OFF 0
#define A_LO_OFF (MT * ASTR * 2)                 // 18432
#define B_HI_OFF (A_LO_OFF + MT * ASTR * 2)      // 36864
#define B_LO_OFF (B_HI_OFF + 128 * ASTR * 2)     // 55296
#define HMMA_SMEM (B_LO_OFF + 128 * ASTR * 2)    // 73728 B -> 2 CTAs/SM

__device__ __forceinline__ void ldm_x4(uint32_t* r, uint32_t addr) {
    asm volatile("ldmatrix.sync.aligned.m8n8.x4.shared.b16 {%0,%1,%2,%3}, [%4];"
                 : "=r"(r[0]), "=r"(r[1]), "=r"(r[2]), "=r"(r[3]) : "r"(addr));
}
__device__ __forceinline__ void ldm_x2(uint32_t* r, uint32_t addr) {
    asm volatile("ldmatrix.sync.aligned.m8n8.x2.shared.b16 {%0,%1}, [%2];"
                 : "=r"(r[0]), "=r"(r[1]) : "r"(addr));
}
__device__ __forceinline__ void mma_bf16(float* c, const uint32_t* a, const uint32_t* b) {
    asm volatile("mma.sync.aligned.m16n8k16.row.col.f32.bf16.bf16.f32 "
                 "{%0,%1,%2,%3}, {%4,%5,%6,%7}, {%8,%9}, {%0,%1,%2,%3};"
                 : "+f"(c[0]), "+f"(c[1]), "+f"(c[2]), "+f"(c[3])
                 : "r"(a[0]), "r"(a[1]), "r"(a[2]), "r"(a[3]), "r"(b[0]), "r"(b[1]));
}

__global__ void __launch_bounds__(256, 2)
gemm_hmma_kernel(const float* __restrict__ feat,
                 const float* __restrict__ b0, const float* __restrict__ scale0,
                 const float* __restrict__ offset0, float* __restrict__ out)
{
    extern __shared__ char smem[];
    const uint32_t sb = smem_u32(smem);
    const int tid  = threadIdx.x;
    const int warp = tid >> 5;
    const int lane = tid & 31;
    const int mw   = warp >> 2;   // 0..1
    const int nw   = warp & 3;    // 0..3
    const int h    = blockIdx.x & 1;               // 0: f0/W0, 1: Z/W1
    const int row0 = (blockIdx.x >> 1) * MT;

    float acc[4][4][4];
#pragma unroll
    for (int mi = 0; mi < 4; ++mi)
#pragma unroll
        for (int ni = 0; ni < 4; ++ni)
#pragma unroll
            for (int j = 0; j < 4; ++j) acc[mi][ni][j] = 0.f;

    const int a_row  = mw * 64 + (lane & 15);
    const int a_coff = (lane >> 4) * 8;
    const int b_row  = nw * 32 + (lane & 7);
    const int b_koff = ((lane >> 3) & 1) * 8;
    const __nv_bfloat16* Whi_h = g_Whi + (size_t)h * 128 * 256;
    const __nv_bfloat16* Wlo_h = g_Wlo + (size_t)h * 128 * 256;

    for (int kc = 0; kc < 4; ++kc) {
        // A tile: 128 rows x 16 float4 = 2048 slots, 8 iters @256 thr
#pragma unroll
        for (int j = 0; j < 8; ++j) {
            int i = tid + j * 256;
            int r = i >> 4, c4 = (i & 15) * 4;
            int grow = row0 + r;
            float4 v = make_float4(0.f, 0.f, 0.f, 0.f);
            if (grow < N_NODES)
                v = *reinterpret_cast<const float4*>(feat + (size_t)grow * D_IN + kc * KCH + c4);
            __nv_bfloat16 h0 = __float2bfloat16(v.x), h1 = __float2bfloat16(v.y);
            __nv_bfloat16 h2 = __float2bfloat16(v.z), h3 = __float2bfloat16(v.w);
            __nv_bfloat16 l0 = __float2bfloat16(v.x - __bfloat162float(h0));
            __nv_bfloat16 l1 = __float2bfloat16(v.y - __bfloat162float(h1));
            __nv_bfloat16 l2 = __float2bfloat16(v.z - __bfloat162float(h2));
            __nv_bfloat16 l3 = __float2bfloat16(v.w - __bfloat162float(h3));
            unsigned long long ph =
                (unsigned long long)__bfloat16_as_ushort(h0)
              | ((unsigned long long)__bfloat16_as_ushort(h1) << 16)
              | ((unsigned long long)__bfloat16_as_ushort(h2) << 32)
              | ((unsigned long long)__bfloat16_as_ushort(h3) << 48);
            unsigned long long pl =
                (unsigned long long)__bfloat16_as_ushort(l0)
              | ((unsigned long long)__bfloat16_as_ushort(l1) << 16)
              | ((unsigned long long)__bfloat16_as_ushort(l2) << 32)
              | ((unsigned long long)__bfloat16_as_ushort(l3) << 48);
            size_t off = ((size_t)r * ASTR + c4) * 2;
            *reinterpret_cast<unsigned long long*>(smem + A_HI_OFF + off) = ph;
            *reinterpret_cast<unsigned long long*>(smem + A_LO_OFF + off) = pl;
        }
        // B tile: 128 rows x 8 chunks = 1024 slots, 4 iters
#pragma unroll
        for (int j = 0; j < 4; ++j) {
            int i = tid + j * 256;
            int n = i >> 3, ch = i & 7;
            size_t off = ((size_t)n * ASTR + ch * 8) * 2;
            *reinterpret_cast<uint4*>(smem + B_HI_OFF + off) =
                *reinterpret_cast<const uint4*>(Whi_h + n * 256 + kc * KCH + ch * 8);
            *reinterpret_cast<uint4*>(smem + B_LO_OFF + off) =
                *reinterpret_cast<const uint4*>(Wlo_h + n * 256 + kc * KCH + ch * 8);
        }
        __syncthreads();

#pragma unroll
        for (int kk = 0; kk < 4; ++kk) {
            uint32_t a_hi[4][4], a_lo[4][4], b[4][2];
            uint32_t acol = kk * 16 + a_coff;
            uint32_t bcol = kk * 16 + b_koff;
#pragma unroll
            for (int mi = 0; mi < 4; ++mi)
                ldm_x4(a_hi[mi], sb + A_HI_OFF + ((a_row + mi * 16) * ASTR + acol) * 2);
#pragma unroll
            for (int ni = 0; ni < 4; ++ni)
                ldm_x2(b[ni], sb + B_HI_OFF + ((b_row + ni * 8) * ASTR + bcol) * 2);
#pragma unroll
            for (int mi = 0; mi < 4; ++mi)
#pragma unroll
                for (int ni = 0; ni < 4; ++ni) mma_bf16(acc[mi][ni], a_hi[mi], b[ni]);
#pragma unroll
            for (int mi = 0; mi < 4; ++mi)
                ldm_x4(a_lo[mi], sb + A_LO_OFF + ((a_row + mi * 16) * ASTR + acol) * 2);
#pragma unroll
            for (int mi = 0; mi < 4; ++mi)
#pragma unroll
                for (int ni = 0; ni < 4; ++ni) mma_bf16(acc[mi][ni], a_lo[mi], b[ni]);
#pragma unroll
            for (int ni = 0; ni < 4; ++ni)
                ldm_x2(b[ni], sb + B_LO_OFF + ((b_row + ni * 8) * ASTR + bcol) * 2);
#pragma unroll
            for (int mi = 0; mi < 4; ++mi)
#pragma unroll
                for (int ni = 0; ni < 4; ++ni) mma_bf16(acc[mi][ni], a_hi[mi], b[ni]);
        }
        __syncthreads();
    }

    const int rloc  = mw * 64 + (lane >> 2);           // + mi*16 (+8)
    const int cbase = nw * 32 + 2 * (lane & 3);

    if (h == 1) {
        // Z path: raw D -> g_Z
#pragma unroll
        for (int mi = 0; mi < 4; ++mi) {
            int r0 = row0 + rloc + mi * 16;
            int r1 = r0 + 8;
#pragma unroll
            for (int ni = 0; ni < 4; ++ni) {
                int col = cbase + ni * 8;
                if (r0 < N_NODES)
                    *reinterpret_cast<float2*>(g_Z + (size_t)r0 * 128 + col) =
                        make_float2(acc[mi][ni][0], acc[mi][ni][1]);
                if (r1 < N_NODES)
                    *reinterpret_cast<float2*>(g_Z + (size_t)r1 * 128 + col) =
                        make_float2(acc[mi][ni][2], acc[mi][ni][3]);
            }
        }
        return;
    }

    // f0 path: LN(relu(D + b0)) -> out[:, :128]
    float2* red = reinterpret_cast<float2*>(smem);     // [128] (s, q) per local row
    if (tid < 128) red[tid] = make_float2(0.f, 0.f);
    __syncthreads();

#pragma unroll
    for (int mi = 0; mi < 4; ++mi) {
        float s0 = 0.f, q0 = 0.f, s1 = 0.f, q1 = 0.f;
#pragma unroll
        for (int ni = 0; ni < 4; ++ni) {
            int col = cbase + ni * 8;
            float bx = __ldg(b0 + col), by = __ldg(b0 + col + 1);
            float v0 = fmaxf(acc[mi][ni][0] + bx, 0.f);
            float v1 = fmaxf(acc[mi][ni][1] + by, 0.f);
            float v2 = fmaxf(acc[mi][ni][2] + bx, 0.f);
            float v3 = fmaxf(acc[mi][ni][3] + by, 0.f);
            acc[mi][ni][0] = v0; acc[mi][ni][1] = v1;
            acc[mi][ni][2] = v2; acc[mi][ni][3] = v3;
            s0 += v0 + v1; q0 += v0 * v0 + v1 * v1;
            s1 += v2 + v3; q1 += v2 * v2 + v3 * v3;
        }
#pragma unroll
        for (int off = 1; off < 4; off <<= 1) {
            s0 += __shfl_xor_sync(0xffffffffu, s0, off);
            q0 += __shfl_xor_sync(0xffffffffu, q0, off);
            s1 += __shfl_xor_sync(0xffffffffu, s1, off);
            q1 += __shfl_xor_sync(0xffffffffu, q1, off);
        }
        if ((lane & 3) == 0) {
            atomicAdd(&red[rloc + mi * 16].x, s0);
            atomicAdd(&red[rloc + mi * 16].y, q0);
            atomicAdd(&red[rloc + mi * 16 + 8].x, s1);
            atomicAdd(&red[rloc + mi * 16 + 8].y, q1);
        }
    }
    __syncthreads();

#pragma unroll
    for (int mi = 0; mi < 4; ++mi) {
        int l0 = rloc + mi * 16, l1 = l0 + 8;
        int r0 = row0 + l0, r1 = row0 + l1;
        float2 sq0 = red[l0], sq1 = red[l1];
        float m0 = sq0.x * (1.f / 128.f);
        float i0 = rsqrtf(sq0.y * (1.f / 128.f) - m0 * m0 + EPSV);
        float m1 = sq1.x * (1.f / 128.f);
        float i1 = rsqrtf(sq1.y * (1.f / 128.f) - m1 * m1 + EPSV);
#pragma unroll
        for (int ni = 0; ni < 4; ++ni) {
            int col = cbase + ni * 8;
            float sx = __ldg(scale0 + col), sy = __ldg(scale0 + col + 1);
            float ox = __ldg(offset0 + col), oy = __ldg(offset0 + col + 1);
            if (r0 < N_NODES)
                *reinterpret_cast<float2*>(out + (size_t)r0 * 256 + col) =
                    make_float2((acc[mi][ni][0] - m0) * i0 * sx + ox,
                                (acc[mi][ni][1] - m0) * i0 * sy + oy);
            if (r1 < N_NODES)
                *reinterpret_cast<float2*>(out + (size_t)r1 * 256 + col) =
                    make_float2((acc[mi][ni][2] - m1) * i1 * sx + ox,
                                (acc[mi][ni][3] - m1) * i1 * sy + oy);
        }
    }
}

// ---------------- SpMM: warp owns 32 edges; 8-deep gather/RED unroll ------------------
#define EPW 32
__global__ void __launch_bounds__(256)
spmm_kernel(const int* __restrict__ erow, const int* __restrict__ ecol,
            const float* __restrict__ eval)
{
    const int warp_id = blockIdx.x * 8 + (threadIdx.x >> 5);
    const int lane = threadIdx.x & 31;
    const int base = warp_id * EPW;
    if (base >= N_EDGES) return;

    int   my_r = __ldg(erow + base + lane);
    int   my_c = __ldg(ecol + base + lane);
    float my_v = __ldg(eval + base + lane);

    const float* Zl  = g_Z  + lane * 4;
    float*       H1l = g_H1 + lane * 4;

#pragma unroll
    for (int jo = 0; jo < EPW; jo += 8) {
        int c[8], r[8]; float v[8];
#pragma unroll
        for (int t = 0; t < 8; ++t) {
            c[t] = __shfl_sync(0xffffffffu, my_c, jo + t);
            r[t] = __shfl_sync(0xffffffffu, my_r, jo + t);
            v[t] = __shfl_sync(0xffffffffu, my_v, jo + t);
        }
        float4 z[8];
#pragma unroll
        for (int t = 0; t < 8; ++t)
            z[t] = *reinterpret_cast<const float4*>(Zl + (size_t)c[t] * 128);
#pragma unroll
        for (int t = 0; t < 8; ++t)
            asm volatile("red.global.add.v4.f32 [%0], {%1, %2, %3, %4};"
                         :: "l"(H1l + (size_t)r[t] * 128),
                            "f"(v[t] * z[t].x), "f"(v[t] * z[t].y),
                            "f"(v[t] * z[t].z), "f"(v[t] * z[t].w) : "memory");
    }
}

// ---------------- f1 epilogue: out[:, 128:] = LN(relu(H1 + b1)) ----------------
__global__ void __launch_bounds__(256)
ln1_kernel(const float* __restrict__ b1, const float* __restrict__ scale1,
           const float* __restrict__ offset1, float* __restrict__ out)
{
    int row = blockIdx.x * 8 + (threadIdx.x >> 5);
    if (row >= N_NODES) return;
    int lane = threadIdx.x & 31;
    float4 h = *reinterpret_cast<const float4*>(g_H1 + (size_t)row * 128 + lane * 4);
    float4 b = *reinterpret_cast<const float4*>(b1 + lane * 4);
    h.x = fmaxf(h.x + b.x, 0.f);
    h.y = fmaxf(h.y + b.y, 0.f);
    h.z = fmaxf(h.z + b.z, 0.f);
    h.w = fmaxf(h.w + b.w, 0.f);
    float s = h.x + h.y + h.z + h.w;
    float q = h.x * h.x + h.y * h.y + h.z * h.z + h.w * h.w;
#pragma unroll
    for (int off = 16; off > 0; off >>= 1) {
        s += __shfl_xor_sync(0xffffffffu, s, off);
        q += __shfl_xor_sync(0xffffffffu, q, off);
    }
    float mean = s * (1.f / 128.f);
    float var  = q * (1.f / 128.f) - mean * mean;
    float inv  = rsqrtf(var + EPSV);
    float4 sc = *reinterpret_cast<const float4*>(scale1 + lane * 4);
    float4 of = *reinterpret_cast<const float4*>(offset1 + lane * 4);
    float4 w;
    w.x = (h.x - mean) * inv * sc.x + of.x;
    w.y = (h.y - mean) * inv * sc.y + of.y;
    w.z = (h.z - mean) * inv * sc.z + of.z;
    w.w = (h.w - mean) * inv * sc.w + of.w;
    *reinterpret_cast<float4*>(out + (size_t)row * 256 + 128 + lane * 4) = w;
}

extern "C" void kernel_launch(void* const* d_in, const int* in_sizes, int n_in,
                              void* d_out, int out_size)
{
    const float* feat    = (const float*)d_in[0];
    const float* W0      = (const float*)d_in[1];
    const float* b0      = (const float*)d_in[2];
    const float* scale0  = (const float*)d_in[3];
    const float* offset0 = (const float*)d_in[4];
    const float* W1      = (const float*)d_in[5];
    const float* b1      = (const float*)d_in[6];
    const float* scale1  = (const float*)d_in[7];
    const float* offset1 = (const float*)d_in[8];
    const int*   erow    = (const int*)d_in[9];
    const int*   ecol    = (const int*)d_in[10];
    const float* eval    = (const float*)d_in[11];
    float* out = (float*)d_out;

    cudaFuncSetAttribute(gemm_hmma_kernel,
                         cudaFuncAttributeMaxDynamicSharedMemorySize, HMMA_SMEM);

    prep_kernel<<<256 + (N_NODES * D_OUT / 4 + 255) / 256, 256>>>(W0, W1);
    gemm_hmma_kernel<<<2 * ((N_NODES + MT - 1) / MT), 256, HMMA_SMEM>>>(
        feat, b0, scale0, offset0, out);
    spmm_kernel<<<(N_EDGES / EPW + 7) / 8, 256>>>(erow, ecol, eval);
    ln1_kernel<<<(N_NODES + 7) / 8, 256>>>(b1, scale1, offset1, out);
}

// round 15
// speedup vs baseline: 1.4452x; 1.0109x over previous
#include <cuda_runtime.h>
#include <cuda_bf16.h>
#include <cstdint>

#define N_NODES 50000
#define N_EDGES 800000
#define D_IN    256
#define D_OUT   128
#define EPSV    1e-9f

// Scratch (allocation-free rule: __device__ globals)
__device__ float g_Z [(size_t)N_NODES * D_OUT];   // Z = feat @ W1   [N, 128]
__device__ float g_H1[(size_t)N_NODES * D_OUT];   // H1 = A @ Z      [N, 128]
// W pre-transposed to [n][k] and bf16-split: B[n][k] = W[k][n] (n<128 -> W0, else W1)
__device__ __nv_bfloat16 g_Whi[256 * 256];
__device__ __nv_bfloat16 g_Wlo[256 * 256];

__device__ __forceinline__ uint32_t smem_u32(const void* p) {
    uint32_t a;
    asm("{ .reg .u64 t; cvta.to.shared.u64 t, %1; cvt.u32.u64 %0, t; }" : "=r"(a) : "l"(p));
    return a;
}

// ---------------- prep: W split + zero H1 in one launch ----------------
__global__ void prep_kernel(const float* __restrict__ W0, const float* __restrict__ W1) {
    int blk = blockIdx.x;
    if (blk < 256) {
        int id = blk * 256 + threadIdx.x;      // 65536
        int n = id >> 8, k = id & 255;
        float w = (n < 128) ? __ldg(W0 + k * 128 + n) : __ldg(W1 + k * 128 + (n - 128));
        __nv_bfloat16 h = __float2bfloat16(w);
        float lo = w - __bfloat162float(h);
        g_Whi[n * 256 + k] = h;
        g_Wlo[n * 256 + k] = __float2bfloat16(lo);
    } else {
        int idx = (blk - 256) * 256 + threadIdx.x;
        const int total = N_NODES * D_OUT / 4;
        if (idx < total)
            reinterpret_cast<float4*>(g_H1)[idx] = make_float4(0.f, 0.f, 0.f, 0.f);
    }
}

// ---------------- HMMA GEMM halves (templated on H) --------------------------------
// H=0 -> out[:, :128] = LN(relu(feat@W0+b0)); H=1 -> g_Z = feat@W1 (raw).
// CTA: 256 threads / 8 warps, warp grid 2(M) x 4(N), warp tile 64x32, tile M=128 N=128.
#define MT   128
#define KCH  64
#define ASTR 72                         // bf16 row stride (144B = 9 x 16B, ldmatrix conflict-free)
#define A_HI_OFF 0
#define A_LO_OFF (MT * ASTR * 2)                 // 18432
#define B_HI_OFF (A_LO_OFF + MT * ASTR * 2)      // 36864
#define B_LO_OFF (B_HI_OFF + 128 * ASTR * 2)     // 55296
#define HMMA_SMEM (B_LO_OFF + 128 * ASTR * 2)    // 73728 B -> 2 CTAs/SM

__device__ __forceinline__ void ldm_x4(uint32_t* r, uint32_t addr) {
    asm volatile("ldmatrix.sync.aligned.m8n8.x4.shared.b16 {%0,%1,%2,%3}, [%4];"
                 : "=r"(r[0]), "=r"(r[1]), "=r"(r[2]), "=r"(r[3]) : "r"(addr));
}
__device__ __forceinline__ void ldm_x2(uint32_t* r, uint32_t addr) {
    asm volatile("ldmatrix.sync.aligned.m8n8.x2.shared.b16 {%0,%1}, [%2];"
                 : "=r"(r[0]), "=r"(r[1]) : "r"(addr));
}
__device__ __forceinline__ void mma_bf16(float* c, const uint32_t* a, const uint32_t* b) {
    asm volatile("mma.sync.aligned.m16n8k16.row.col.f32.bf16.bf16.f32 "
                 "{%0,%1,%2,%3}, {%4,%5,%6,%7}, {%8,%9}, {%0,%1,%2,%3};"
                 : "+f"(c[0]), "+f"(c[1]), "+f"(c[2]), "+f"(c[3])
                 : "r"(a[0]), "r"(a[1]), "r"(a[2]), "r"(a[3]), "r"(b[0]), "r"(b[1]));
}

template <int H>
__global__ void __launch_bounds__(256, 2)
gemm_hmma_kernel(const float* __restrict__ feat,
                 const float* __restrict__ b0, const float* __restrict__ scale0,
                 const float* __restrict__ offset0, float* __restrict__ out)
{
    extern __shared__ char smem[];
    const uint32_t sb = smem_u32(smem);
    const int tid  = threadIdx.x;
    const int warp = tid >> 5;
    const int lane = tid & 31;
    const int mw   = warp >> 2;   // 0..1
    const int nw   = warp & 3;    // 0..3
    const int row0 = blockIdx.x * MT;

    float acc[4][4][4];
#pragma unroll
    for (int mi = 0; mi < 4; ++mi)
#pragma unroll
        for (int ni = 0; ni < 4; ++ni)
#pragma unroll
            for (int j = 0; j < 4; ++j) acc[mi][ni][j] = 0.f;

    const int a_row  = mw * 64 + (lane & 15);
    const int a_coff = (lane >> 4) * 8;
    const int b_row  = nw * 32 + (lane & 7);
    const int b_koff = ((lane >> 3) & 1) * 8;
    const __nv_bfloat16* Whi_h = g_Whi + (size_t)H * 128 * 256;
    const __nv_bfloat16* Wlo_h = g_Wlo + (size_t)H * 128 * 256;

    for (int kc = 0; kc < 4; ++kc) {
        // A tile: 128 rows x 16 float4 = 2048 slots, 8 iters @256 thr
#pragma unroll
        for (int j = 0; j < 8; ++j) {
            int i = tid + j * 256;
            int r = i >> 4, c4 = (i & 15) * 4;
            int grow = row0 + r;
            float4 v = make_float4(0.f, 0.f, 0.f, 0.f);
            if (grow < N_NODES)
                v = *reinterpret_cast<const float4*>(feat + (size_t)grow * D_IN + kc * KCH + c4);
            __nv_bfloat16 h0 = __float2bfloat16(v.x), h1 = __float2bfloat16(v.y);
            __nv_bfloat16 h2 = __float2bfloat16(v.z), h3 = __float2bfloat16(v.w);
            __nv_bfloat16 l0 = __float2bfloat16(v.x - __bfloat162float(h0));
            __nv_bfloat16 l1 = __float2bfloat16(v.y - __bfloat162float(h1));
            __nv_bfloat16 l2 = __float2bfloat16(v.z - __bfloat162float(h2));
            __nv_bfloat16 l3 = __float2bfloat16(v.w - __bfloat162float(h3));
            unsigned long long ph =
                (unsigned long long)__bfloat16_as_ushort(h0)
              | ((unsigned long long)__bfloat16_as_ushort(h1) << 16)
              | ((unsigned long long)__bfloat16_as_ushort(h2) << 32)
              | ((unsigned long long)__bfloat16_as_ushort(h3) << 48);
            unsigned long long pl =
                (unsigned long long)__bfloat16_as_ushort(l0)
              | ((unsigned long long)__bfloat16_as_ushort(l1) << 16)
              | ((unsigned long long)__bfloat16_as_ushort(l2) << 32)
              | ((unsigned long long)__bfloat16_as_ushort(l3) << 48);
            size_t off = ((size_t)r * ASTR + c4) * 2;
            *reinterpret_cast<unsigned long long*>(smem + A_HI_OFF + off) = ph;
            *reinterpret_cast<unsigned long long*>(smem + A_LO_OFF + off) = pl;
        }
        // B tile: 128 rows x 8 chunks = 1024 slots, 4 iters
#pragma unroll
        for (int j = 0; j < 4; ++j) {
            int i = tid + j * 256;
            int n = i >> 3, ch = i & 7;
            size_t off = ((size_t)n * ASTR + ch * 8) * 2;
            *reinterpret_cast<uint4*>(smem + B_HI_OFF + off) =
                *reinterpret_cast<const uint4*>(Whi_h + n * 256 + kc * KCH + ch * 8);
            *reinterpret_cast<uint4*>(smem + B_LO_OFF + off) =
                *reinterpret_cast<const uint4*>(Wlo_h + n * 256 + kc * KCH + ch * 8);
        }
        __syncthreads();

#pragma unroll
        for (int kk = 0; kk < 4; ++kk) {
            uint32_t a_hi[4][4], a_lo[4][4], b[4][2];
            uint32_t acol = kk * 16 + a_coff;
            uint32_t bcol = kk * 16 + b_koff;
#pragma unroll
            for (int mi = 0; mi < 4; ++mi)
                ldm_x4(a_hi[mi], sb + A_HI_OFF + ((a_row + mi * 16) * ASTR + acol) * 2);
#pragma unroll
            for (int ni = 0; ni < 4; ++ni)
                ldm_x2(b[ni], sb + B_HI_OFF + ((b_row + ni * 8) * ASTR + bcol) * 2);
#pragma unroll
            for (int mi = 0; mi < 4; ++mi)
#pragma unroll
                for (int ni = 0; ni < 4; ++ni) mma_bf16(acc[mi][ni], a_hi[mi], b[ni]);
#pragma unroll
            for (int mi = 0; mi < 4; ++mi)
                ldm_x4(a_lo[mi], sb + A_LO_OFF + ((a_row + mi * 16) * ASTR + acol) * 2);
#pragma unroll
            for (int mi = 0; mi < 4; ++mi)
#pragma unroll
                for (int ni = 0; ni < 4; ++ni) mma_bf16(acc[mi][ni], a_lo[mi], b[ni]);
#pragma unroll
            for (int ni = 0; ni < 4; ++ni)
                ldm_x2(b[ni], sb + B_LO_OFF + ((b_row + ni * 8) * ASTR + bcol) * 2);
#pragma unroll
            for (int mi = 0; mi < 4; ++mi)
#pragma unroll
                for (int ni = 0; ni < 4; ++ni) mma_bf16(acc[mi][ni], a_hi[mi], b[ni]);
        }
        __syncthreads();
    }

    const int rloc  = mw * 64 + (lane >> 2);           // + mi*16 (+8)
    const int cbase = nw * 32 + 2 * (lane & 3);

    if (H == 1) {
        // Z path: raw D -> g_Z
#pragma unroll
        for (int mi = 0; mi < 4; ++mi) {
            int r0 = row0 + rloc + mi * 16;
            int r1 = r0 + 8;
#pragma unroll
            for (int ni = 0; ni < 4; ++ni) {
                int col = cbase + ni * 8;
                if (r0 < N_NODES)
                    *reinterpret_cast<float2*>(g_Z + (size_t)r0 * 128 + col) =
                        make_float2(acc[mi][ni][0], acc[mi][ni][1]);
                if (r1 < N_NODES)
                    *reinterpret_cast<float2*>(g_Z + (size_t)r1 * 128 + col) =
                        make_float2(acc[mi][ni][2], acc[mi][ni][3]);
            }
        }
        return;
    }

    // f0 path: LN(relu(D + b0)) -> out[:, :128]
    float2* red = reinterpret_cast<float2*>(smem);     // [128] (s, q) per local row
    if (tid < 128) red[tid] = make_float2(0.f, 0.f);
    __syncthreads();

#pragma unroll
    for (int mi = 0; mi < 4; ++mi) {
        float s0 = 0.f, q0 = 0.f, s1 = 0.f, q1 = 0.f;
#pragma unroll
        for (int ni = 0; ni < 4; ++ni) {
            int col = cbase + ni * 8;
            float bx = __ldg(b0 + col), by = __ldg(b0 + col + 1);
            float v0 = fmaxf(acc[mi][ni][0] + bx, 0.f);
            float v1 = fmaxf(acc[mi][ni][1] + by, 0.f);
            float v2 = fmaxf(acc[mi][ni][2] + bx, 0.f);
            float v3 = fmaxf(acc[mi][ni][3] + by, 0.f);
            acc[mi][ni][0] = v0; acc[mi][ni][1] = v1;
            acc[mi][ni][2] = v2; acc[mi][ni][3] = v3;
            s0 += v0 + v1; q0 += v0 * v0 + v1 * v1;
            s1 += v2 + v3; q1 += v2 * v2 + v3 * v3;
        }
#pragma unroll
        for (int off = 1; off < 4; off <<= 1) {
            s0 += __shfl_xor_sync(0xffffffffu, s0, off);
            q0 += __shfl_xor_sync(0xffffffffu, q0, off);
            s1 += __shfl_xor_sync(0xffffffffu, s1, off);
            q1 += __shfl_xor_sync(0xffffffffu, q1, off);
        }
        if ((lane & 3) == 0) {
            atomicAdd(&red[rloc + mi * 16].x, s0);
            atomicAdd(&red[rloc + mi * 16].y, q0);
            atomicAdd(&red[rloc + mi * 16 + 8].x, s1);
            atomicAdd(&red[rloc + mi * 16 + 8].y, q1);
        }
    }
    __syncthreads();

#pragma unroll
    for (int mi = 0; mi < 4; ++mi) {
        int l0 = rloc + mi * 16, l1 = l0 + 8;
        int r0 = row0 + l0, r1 = row0 + l1;
        float2 sq0 = red[l0], sq1 = red[l1];
        float m0 = sq0.x * (1.f / 128.f);
        float i0 = rsqrtf(sq0.y * (1.f / 128.f) - m0 * m0 + EPSV);
        float m1 = sq1.x * (1.f / 128.f);
        float i1 = rsqrtf(sq1.y * (1.f / 128.f) - m1 * m1 + EPSV);
#pragma unroll
        for (int ni = 0; ni < 4; ++ni) {
            int col = cbase + ni * 8;
            float sx = __ldg(scale0 + col), sy = __ldg(scale0 + col + 1);
            float ox = __ldg(offset0 + col), oy = __ldg(offset0 + col + 1);
            if (r0 < N_NODES)
                *reinterpret_cast<float2*>(out + (size_t)r0 * 256 + col) =
                    make_float2((acc[mi][ni][0] - m0) * i0 * sx + ox,
                                (acc[mi][ni][1] - m0) * i0 * sy + oy);
            if (r1 < N_NODES)
                *reinterpret_cast<float2*>(out + (size_t)r1 * 256 + col) =
                    make_float2((acc[mi][ni][2] - m1) * i1 * sx + ox,
                                (acc[mi][ni][3] - m1) * i1 * sy + oy);
        }
    }
}

// ---------------- SpMM: warp owns 32 edges; 8-deep gather/RED unroll ------------------
#define EPW 32
__global__ void __launch_bounds__(256)
spmm_kernel(const int* __restrict__ erow, const int* __restrict__ ecol,
            const float* __restrict__ eval)
{
    const int warp_id = blockIdx.x * 8 + (threadIdx.x >> 5);
    const int lane = threadIdx.x & 31;
    const int base = warp_id * EPW;
    if (base >= N_EDGES) return;

    int   my_r = __ldg(erow + base + lane);
    int   my_c = __ldg(ecol + base + lane);
    float my_v = __ldg(eval + base + lane);

    const float* Zl  = g_Z  + lane * 4;
    float*       H1l = g_H1 + lane * 4;

#pragma unroll
    for (int jo = 0; jo < EPW; jo += 8) {
        int c[8], r[8]; float v[8];
#pragma unroll
        for (int t = 0; t < 8; ++t) {
            c[t] = __shfl_sync(0xffffffffu, my_c, jo + t);
            r[t] = __shfl_sync(0xffffffffu, my_r, jo + t);
            v[t] = __shfl_sync(0xffffffffu, my_v, jo + t);
        }
        float4 z[8];
#pragma unroll
        for (int t = 0; t < 8; ++t)
            z[t] = *reinterpret_cast<const float4*>(Zl + (size_t)c[t] * 128);
#pragma unroll
        for (int t = 0; t < 8; ++t)
            asm volatile("red.global.add.v4.f32 [%0], {%1, %2, %3, %4};"
                         :: "l"(H1l + (size_t)r[t] * 128),
                            "f"(v[t] * z[t].x), "f"(v[t] * z[t].y),
                            "f"(v[t] * z[t].z), "f"(v[t] * z[t].w) : "memory");
    }
}

// ---------------- f1 epilogue: out[:, 128:] = LN(relu(H1 + b1)) ----------------
__global__ void __launch_bounds__(256)
ln1_kernel(const float* __restrict__ b1, const float* __restrict__ scale1,
           const float* __restrict__ offset1, float* __restrict__ out)
{
    int row = blockIdx.x * 8 + (threadIdx.x >> 5);
    if (row >= N_NODES) return;
    int lane = threadIdx.x & 31;
    float4 h = *reinterpret_cast<const float4*>(g_H1 + (size_t)row * 128 + lane * 4);
    float4 b = *reinterpret_cast<const float4*>(b1 + lane * 4);
    h.x = fmaxf(h.x + b.x, 0.f);
    h.y = fmaxf(h.y + b.y, 0.f);
    h.z = fmaxf(h.z + b.z, 0.f);
    h.w = fmaxf(h.w + b.w, 0.f);
    float s = h.x + h.y + h.z + h.w;
    float q = h.x * h.x + h.y * h.y + h.z * h.z + h.w * h.w;
#pragma unroll
    for (int off = 16; off > 0; off >>= 1) {
        s += __shfl_xor_sync(0xffffffffu, s, off);
        q += __shfl_xor_sync(0xffffffffu, q, off);
    }
    float mean = s * (1.f / 128.f);
    float var  = q * (1.f / 128.f) - mean * mean;
    float inv  = rsqrtf(var + EPSV);
    float4 sc = *reinterpret_cast<const float4*>(scale1 + lane * 4);
    float4 of = *reinterpret_cast<const float4*>(offset1 + lane * 4);
    float4 w;
    w.x = (h.x - mean) * inv * sc.x + of.x;
    w.y = (h.y - mean) * inv * sc.y + of.y;
    w.z = (h.z - mean) * inv * sc.z + of.z;
    w.w = (h.w - mean) * inv * sc.w + of.w;
    *reinterpret_cast<float4*>(out + (size_t)row * 256 + 128 + lane * 4) = w;
}

extern "C" void kernel_launch(void* const* d_in, const int* in_sizes, int n_in,
                              void* d_out, int out_size)
{
    const float* feat    = (const float*)d_in[0];
    const float* W0      = (const float*)d_in[1];
    const float* b0      = (const float*)d_in[2];
    const float* scale0  = (const float*)d_in[3];
    const float* offset0 = (const float*)d_in[4];
    const float* W1      = (const float*)d_in[5];
    const float* b1      = (const float*)d_in[6];
    const float* scale1  = (const float*)d_in[7];
    const float* offset1 = (const float*)d_in[8];
    const int*   erow    = (const int*)d_in[9];
    const int*   ecol    = (const int*)d_in[10];
    const float* eval    = (const float*)d_in[11];
    float* out = (float*)d_out;

    cudaFuncSetAttribute(gemm_hmma_kernel<0>,
                         cudaFuncAttributeMaxDynamicSharedMemorySize, HMMA_SMEM);
    cudaFuncSetAttribute(gemm_hmma_kernel<1>,
                         cudaFuncAttributeMaxDynamicSharedMemorySize, HMMA_SMEM);

    // Fork/join resources: created fresh each call (kernel_launch runs only a few
    // times — correctness + capture; graph replays don't execute host code).
    // No device-memory allocation involved.
    cudaStream_t s2;
    cudaEvent_t ev_fork, ev_join;
    cudaStreamCreateWithFlags(&s2, cudaStreamNonBlocking);
    cudaEventCreateWithFlags(&ev_fork, cudaEventDisableTiming);
    cudaEventCreateWithFlags(&ev_join, cudaEventDisableTiming);

    const int GRID_T = (N_NODES + MT - 1) / MT;   // 391

    // default stream: prep -> Z-gemm
    prep_kernel<<<256 + (N_NODES * D_OUT / 4 + 255) / 256, 256>>>(W0, W1);
    gemm_hmma_kernel<1><<<GRID_T, 256, HMMA_SMEM>>>(feat, b0, scale0, offset0, out);
    cudaEventRecord(ev_fork, 0);

    // fork: f0-gemm on s2, concurrent with spmm+ln1 on default stream
    cudaStreamWaitEvent(s2, ev_fork, 0);
    gemm_hmma_kernel<0><<<GRID_T, 256, HMMA_SMEM, s2>>>(feat, b0, scale0, offset0, out);
    cudaEventRecord(ev_join, s2);

    spmm_kernel<<<(N_EDGES / EPW + 7) / 8, 256>>>(erow, ecol, eval);
    ln1_kernel<<<(N_NODES + 7) / 8, 256>>>(b1, scale1, offset1, out);

    // join back to the capture-origin stream
    cudaStreamWaitEvent(0, ev_join, 0);
}

// round 16
// speedup vs baseline: 1.4638x; 1.0128x over previous
#include <cuda_runtime.h>
#include <cuda_bf16.h>
#include <cuda_fp16.h>
#include <cstdint>

#define N_NODES 50000
#define N_EDGES 800000
#define D_IN    256
#define D_OUT   128
#define EPSV    1e-9f

// Scratch (allocation-free rule: __device__ globals)
__device__ __half g_Z [(size_t)N_NODES * D_OUT];  // Z = feat @ W1   [N, 128] (fp16)
__device__ float  g_H1[(size_t)N_NODES * D_OUT];  // H1 = A @ Z      [N, 128] (fp32)
// W pre-transposed to [n][k] and bf16-split: B[n][k] = W[k][n] (n<128 -> W0, else W1)
__device__ __nv_bfloat16 g_Whi[256 * 256];
__device__ __nv_bfloat16 g_Wlo[256 * 256];

__device__ __forceinline__ uint32_t smem_u32(const void* p) {
    uint32_t a;
    asm("{ .reg .u64 t; cvta.to.shared.u64 t, %1; cvt.u32.u64 %0, t; }" : "=r"(a) : "l"(p));
    return a;
}

// ---------------- prep: W split + zero H1 in one launch ----------------
__global__ void prep_kernel(const float* __restrict__ W0, const float* __restrict__ W1) {
    int blk = blockIdx.x;
    if (blk < 256) {
        int id = blk * 256 + threadIdx.x;      // 65536
        int n = id >> 8, k = id & 255;
        float w = (n < 128) ? __ldg(W0 + k * 128 + n) : __ldg(W1 + k * 128 + (n - 128));
        __nv_bfloat16 h = __float2bfloat16(w);
        float lo = w - __bfloat162float(h);
        g_Whi[n * 256 + k] = h;
        g_Wlo[n * 256 + k] = __float2bfloat16(lo);
    } else {
        int idx = (blk - 256) * 256 + threadIdx.x;
        const int total = N_NODES * D_OUT / 4;
        if (idx < total)
            reinterpret_cast<float4*>(g_H1)[idx] = make_float4(0.f, 0.f, 0.f, 0.f);
    }
}

// ---------------- HMMA GEMM halves (templated on H) --------------------------------
// H=0 -> out[:, :128] = LN(relu(feat@W0+b0)); H=1 -> g_Z = feat@W1 (fp16 raw).
#define MT   128
#define KCH  64
#define ASTR 72                         // bf16 row stride (144B = 9 x 16B, ldmatrix conflict-free)
#define A_HI_OFF 0
#define A_LO_OFF (MT * ASTR * 2)                 // 18432
#define B_HI_OFF (A_LO_OFF + MT * ASTR * 2)      // 36864
#define B_LO_OFF (B_HI_OFF + 128 * ASTR * 2)     // 55296
#define HMMA_SMEM (B_LO_OFF + 128 * ASTR * 2)    // 73728 B -> 2 CTAs/SM

__device__ __forceinline__ void ldm_x4(uint32_t* r, uint32_t addr) {
    asm volatile("ldmatrix.sync.aligned.m8n8.x4.shared.b16 {%0,%1,%2,%3}, [%4];"
                 : "=r"(r[0]), "=r"(r[1]), "=r"(r[2]), "=r"(r[3]) : "r"(addr));
}
__device__ __forceinline__ void ldm_x2(uint32_t* r, uint32_t addr) {
    asm volatile("ldmatrix.sync.aligned.m8n8.x2.shared.b16 {%0,%1}, [%2];"
                 : "=r"(r[0]), "=r"(r[1]) : "r"(addr));
}
__device__ __forceinline__ void mma_bf16(float* c, const uint32_t* a, const uint32_t* b) {
    asm volatile("mma.sync.aligned.m16n8k16.row.col.f32.bf16.bf16.f32 "
                 "{%0,%1,%2,%3}, {%4,%5,%6,%7}, {%8,%9}, {%0,%1,%2,%3};"
                 : "+f"(c[0]), "+f"(c[1]), "+f"(c[2]), "+f"(c[3])
                 : "r"(a[0]), "r"(a[1]), "r"(a[2]), "r"(a[3]), "r"(b[0]), "r"(b[1]));
}

template <int H>
__global__ void __launch_bounds__(256, 2)
gemm_hmma_kernel(const float* __restrict__ feat,
                 const float* __restrict__ b0, const float* __restrict__ scale0,
                 const float* __restrict__ offset0, float* __restrict__ out)
{
    extern __shared__ char smem[];
    const uint32_t sb = smem_u32(smem);
    const int tid  = threadIdx.x;
    const int warp = tid >> 5;
    const int lane = tid & 31;
    const int mw   = warp >> 2;   // 0..1
    const int nw   = warp & 3;    // 0..3
    const int row0 = blockIdx.x * MT;

    float acc[4][4][4];
#pragma unroll
    for (int mi = 0; mi < 4; ++mi)
#pragma unroll
        for (int ni = 0; ni < 4; ++ni)
#pragma unroll
            for (int j = 0; j < 4; ++j) acc[mi][ni][j] = 0.f;

    const int a_row  = mw * 64 + (lane & 15);
    const int a_coff = (lane >> 4) * 8;
    const int b_row  = nw * 32 + (lane & 7);
    const int b_koff = ((lane >> 3) & 1) * 8;
    const __nv_bfloat16* Whi_h = g_Whi + (size_t)H * 128 * 256;
    const __nv_bfloat16* Wlo_h = g_Wlo + (size_t)H * 128 * 256;

    for (int kc = 0; kc < 4; ++kc) {
        // A tile: 128 rows x 16 float4 = 2048 slots, 8 iters @256 thr
#pragma unroll
        for (int j = 0; j < 8; ++j) {
            int i = tid + j * 256;
            int r = i >> 4, c4 = (i & 15) * 4;
            int grow = row0 + r;
            float4 v = make_float4(0.f, 0.f, 0.f, 0.f);
            if (grow < N_NODES)
                v = *reinterpret_cast<const float4*>(feat + (size_t)grow * D_IN + kc * KCH + c4);
            __nv_bfloat16 h0 = __float2bfloat16(v.x), h1 = __float2bfloat16(v.y);
            __nv_bfloat16 h2 = __float2bfloat16(v.z), h3 = __float2bfloat16(v.w);
            __nv_bfloat16 l0 = __float2bfloat16(v.x - __bfloat162float(h0));
            __nv_bfloat16 l1 = __float2bfloat16(v.y - __bfloat162float(h1));
            __nv_bfloat16 l2 = __float2bfloat16(v.z - __bfloat162float(h2));
            __nv_bfloat16 l3 = __float2bfloat16(v.w - __bfloat162float(h3));
            unsigned long long ph =
                (unsigned long long)__bfloat16_as_ushort(h0)
              | ((unsigned long long)__bfloat16_as_ushort(h1) << 16)
              | ((unsigned long long)__bfloat16_as_ushort(h2) << 32)
              | ((unsigned long long)__bfloat16_as_ushort(h3) << 48);
            unsigned long long pl =
                (unsigned long long)__bfloat16_as_ushort(l0)
              | ((unsigned long long)__bfloat16_as_ushort(l1) << 16)
              | ((unsigned long long)__bfloat16_as_ushort(l2) << 32)
              | ((unsigned long long)__bfloat16_as_ushort(l3) << 48);
            size_t off = ((size_t)r * ASTR + c4) * 2;
            *reinterpret_cast<unsigned long long*>(smem + A_HI_OFF + off) = ph;
            *reinterpret_cast<unsigned long long*>(smem + A_LO_OFF + off) = pl;
        }
        // B tile: 128 rows x 8 chunks = 1024 slots, 4 iters
#pragma unroll
        for (int j = 0; j < 4; ++j) {
            int i = tid + j * 256;
            int n = i >> 3, ch = i & 7;
            size_t off = ((size_t)n * ASTR + ch * 8) * 2;
            *reinterpret_cast<uint4*>(smem + B_HI_OFF + off) =
                *reinterpret_cast<const uint4*>(Whi_h + n * 256 + kc * KCH + ch * 8);
            *reinterpret_cast<uint4*>(smem + B_LO_OFF + off) =
                *reinterpret_cast<const uint4*>(Wlo_h + n * 256 + kc * KCH + ch * 8);
        }
        __syncthreads();

#pragma unroll
        for (int kk = 0; kk < 4; ++kk) {
            uint32_t a_hi[4][4], a_lo[4][4], b[4][2];
            uint32_t acol = kk * 16 + a_coff;
            uint32_t bcol = kk * 16 + b_koff;
#pragma unroll
            for (int mi = 0; mi < 4; ++mi)
                ldm_x4(a_hi[mi], sb + A_HI_OFF + ((a_row + mi * 16) * ASTR + acol) * 2);
#pragma unroll
            for (int ni = 0; ni < 4; ++ni)
                ldm_x2(b[ni], sb + B_HI_OFF + ((b_row + ni * 8) * ASTR + bcol) * 2);
#pragma unroll
            for (int mi = 0; mi < 4; ++mi)
#pragma unroll
                for (int ni = 0; ni < 4; ++ni) mma_bf16(acc[mi][ni], a_hi[mi], b[ni]);
#pragma unroll
            for (int mi = 0; mi < 4; ++mi)
                ldm_x4(a_lo[mi], sb + A_LO_OFF + ((a_row + mi * 16) * ASTR + acol) * 2);
#pragma unroll
            for (int mi = 0; mi < 4; ++mi)
#pragma unroll
                for (int ni = 0; ni < 4; ++ni) mma_bf16(acc[mi][ni], a_lo[mi], b[ni]);
#pragma unroll
            for (int ni = 0; ni < 4; ++ni)
                ldm_x2(b[ni], sb + B_LO_OFF + ((b_row + ni * 8) * ASTR + bcol) * 2);
#pragma unroll
            for (int mi = 0; mi < 4; ++mi)
#pragma unroll
                for (int ni = 0; ni < 4; ++ni) mma_bf16(acc[mi][ni], a_hi[mi], b[ni]);
        }
        __syncthreads();
    }

    const int rloc  = mw * 64 + (lane >> 2);           // + mi*16 (+8)
    const int cbase = nw * 32 + 2 * (lane & 3);

    if (H == 1) {
        // Z path: raw D -> g_Z (fp16)
#pragma unroll
        for (int mi = 0; mi < 4; ++mi) {
            int r0 = row0 + rloc + mi * 16;
            int r1 = r0 + 8;
#pragma unroll
            for (int ni = 0; ni < 4; ++ni) {
                int col = cbase + ni * 8;
                if (r0 < N_NODES)
                    *reinterpret_cast<__half2*>(g_Z + (size_t)r0 * 128 + col) =
                        __floats2half2_rn(acc[mi][ni][0], acc[mi][ni][1]);
                if (r1 < N_NODES)
                    *reinterpret_cast<__half2*>(g_Z + (size_t)r1 * 128 + col) =
                        __floats2half2_rn(acc[mi][ni][2], acc[mi][ni][3]);
            }
        }
        return;
    }

    // f0 path: LN(relu(D + b0)) -> out[:, :128]
    float2* red = reinterpret_cast<float2*>(smem);     // [128] (s, q) per local row
    if (tid < 128) red[tid] = make_float2(0.f, 0.f);
    __syncthreads();

#pragma unroll
    for (int mi = 0; mi < 4; ++mi) {
        float s0 = 0.f, q0 = 0.f, s1 = 0.f, q1 = 0.f;
#pragma unroll
        for (int ni = 0; ni < 4; ++ni) {
            int col = cbase + ni * 8;
            float bx = __ldg(b0 + col), by = __ldg(b0 + col + 1);
            float v0 = fmaxf(acc[mi][ni][0] + bx, 0.f);
            float v1 = fmaxf(acc[mi][ni][1] + by, 0.f);
            float v2 = fmaxf(acc[mi][ni][2] + bx, 0.f);
            float v3 = fmaxf(acc[mi][ni][3] + by, 0.f);
            acc[mi][ni][0] = v0; acc[mi][ni][1] = v1;
            acc[mi][ni][2] = v2; acc[mi][ni][3] = v3;
            s0 += v0 + v1; q0 += v0 * v0 + v1 * v1;
            s1 += v2 + v3; q1 += v2 * v2 + v3 * v3;
        }
#pragma unroll
        for (int off = 1; off < 4; off <<= 1) {
            s0 += __shfl_xor_sync(0xffffffffu, s0, off);
            q0 += __shfl_xor_sync(0xffffffffu, q0, off);
            s1 += __shfl_xor_sync(0xffffffffu, s1, off);
            q1 += __shfl_xor_sync(0xffffffffu, q1, off);
        }
        if ((lane & 3) == 0) {
            atomicAdd(&red[rloc + mi * 16].x, s0);
            atomicAdd(&red[rloc + mi * 16].y, q0);
            atomicAdd(&red[rloc + mi * 16 + 8].x, s1);
            atomicAdd(&red[rloc + mi * 16 + 8].y, q1);
        }
    }
    __syncthreads();

#pragma unroll
    for (int mi = 0; mi < 4; ++mi) {
        int l0 = rloc + mi * 16, l1 = l0 + 8;
        int r0 = row0 + l0, r1 = row0 + l1;
        float2 sq0 = red[l0], sq1 = red[l1];
        float m0 = sq0.x * (1.f / 128.f);
        float i0 = rsqrtf(sq0.y * (1.f / 128.f) - m0 * m0 + EPSV);
        float m1 = sq1.x * (1.f / 128.f);
        float i1 = rsqrtf(sq1.y * (1.f / 128.f) - m1 * m1 + EPSV);
#pragma unroll
        for (int ni = 0; ni < 4; ++ni) {
            int col = cbase + ni * 8;
            float sx = __ldg(scale0 + col), sy = __ldg(scale0 + col + 1);
            float ox = __ldg(offset0 + col), oy = __ldg(offset0 + col + 1);
            if (r0 < N_NODES)
                *reinterpret_cast<float2*>(out + (size_t)r0 * 256 + col) =
                    make_float2((acc[mi][ni][0] - m0) * i0 * sx + ox,
                                (acc[mi][ni][1] - m0) * i0 * sy + oy);
            if (r1 < N_NODES)
                *reinterpret_cast<float2*>(out + (size_t)r1 * 256 + col) =
                    make_float2((acc[mi][ni][2] - m1) * i1 * sx + ox,
                                (acc[mi][ni][3] - m1) * i1 * sy + oy);
        }
    }
}

// ---------------- SpMM: warp owns 32 edges; fp16 gather, fp32 RED --------------------
#define EPW 32
__global__ void __launch_bounds__(256)
spmm_kernel(const int* __restrict__ erow, const int* __restrict__ ecol,
            const float* __restrict__ eval)
{
    const int warp_id = blockIdx.x * 8 + (threadIdx.x >> 5);
    const int lane = threadIdx.x & 31;
    const int base = warp_id * EPW;
    if (base >= N_EDGES) return;

    int   my_r = __ldg(erow + base + lane);
    int   my_c = __ldg(ecol + base + lane);
    float my_v = __ldg(eval + base + lane);

    const __half* Zl  = g_Z  + lane * 4;
    float*        H1l = g_H1 + lane * 4;

#pragma unroll
    for (int jo = 0; jo < EPW; jo += 8) {
        int c[8], r[8]; float v[8];
#pragma unroll
        for (int t = 0; t < 8; ++t) {
            c[t] = __shfl_sync(0xffffffffu, my_c, jo + t);
            r[t] = __shfl_sync(0xffffffffu, my_r, jo + t);
            v[t] = __shfl_sync(0xffffffffu, my_v, jo + t);
        }
        uint2 z[8];
#pragma unroll
        for (int t = 0; t < 8; ++t)
            z[t] = *reinterpret_cast<const uint2*>(Zl + (size_t)c[t] * 128);
#pragma unroll
        for (int t = 0; t < 8; ++t) {
            float2 f01 = __half22float2(*reinterpret_cast<__half2*>(&z[t].x));
            float2 f23 = __half22float2(*reinterpret_cast<__half2*>(&z[t].y));
            asm volatile("red.global.add.v4.f32 [%0], {%1, %2, %3, %4};"
                         :: "l"(H1l + (size_t)r[t] * 128),
                            "f"(v[t] * f01.x), "f"(v[t] * f01.y),
                            "f"(v[t] * f23.x), "f"(v[t] * f23.y) : "memory");
        }
    }
}

// ---------------- f1 epilogue: out[:, 128:] = LN(relu(H1 + b1)) ----------------
__global__ void __launch_bounds__(256)
ln1_kernel(const float* __restrict__ b1, const float* __restrict__ scale1,
           const float* __restrict__ offset1, float* __restrict__ out)
{
    int row = blockIdx.x * 8 + (threadIdx.x >> 5);
    if (row >= N_NODES) return;
    int lane = threadIdx.x & 31;
    float4 h = *reinterpret_cast<const float4*>(g_H1 + (size_t)row * 128 + lane * 4);
    float4 b = *reinterpret_cast<const float4*>(b1 + lane * 4);
    h.x = fmaxf(h.x + b.x, 0.f);
    h.y = fmaxf(h.y + b.y, 0.f);
    h.z = fmaxf(h.z + b.z, 0.f);
    h.w = fmaxf(h.w + b.w, 0.f);
    float s = h.x + h.y + h.z + h.w;
    float q = h.x * h.x + h.y * h.y + h.z * h.z + h.w * h.w;
#pragma unroll
    for (int off = 16; off > 0; off >>= 1) {
        s += __shfl_xor_sync(0xffffffffu, s, off);
        q += __shfl_xor_sync(0xffffffffu, q, off);
    }
    float mean = s * (1.f / 128.f);
    float var  = q * (1.f / 128.f) - mean * mean;
    float inv  = rsqrtf(var + EPSV);
    float4 sc = *reinterpret_cast<const float4*>(scale1 + lane * 4);
    float4 of = *reinterpret_cast<const float4*>(offset1 + lane * 4);
    float4 w;
    w.x = (h.x - mean) * inv * sc.x + of.x;
    w.y = (h.y - mean) * inv * sc.y + of.y;
    w.z = (h.z - mean) * inv * sc.z + of.z;
    w.w = (h.w - mean) * inv * sc.w + of.w;
    *reinterpret_cast<float4*>(out + (size_t)row * 256 + 128 + lane * 4) = w;
}

extern "C" void kernel_launch(void* const* d_in, const int* in_sizes, int n_in,
                              void* d_out, int out_size)
{
    const float* feat    = (const float*)d_in[0];
    const float* W0      = (const float*)d_in[1];
    const float* b0      = (const float*)d_in[2];
    const float* scale0  = (const float*)d_in[3];
    const float* offset0 = (const float*)d_in[4];
    const float* W1      = (const float*)d_in[5];
    const float* b1      = (const float*)d_in[6];
    const float* scale1  = (const float*)d_in[7];
    const float* offset1 = (const float*)d_in[8];
    const int*   erow    = (const int*)d_in[9];
    const int*   ecol    = (const int*)d_in[10];
    const float* eval    = (const float*)d_in[11];
    float* out = (float*)d_out;

    cudaFuncSetAttribute(gemm_hmma_kernel<0>,
                         cudaFuncAttributeMaxDynamicSharedMemorySize, HMMA_SMEM);
    cudaFuncSetAttribute(gemm_hmma_kernel<1>,
                         cudaFuncAttributeMaxDynamicSharedMemorySize, HMMA_SMEM);

    cudaStream_t s2;
    cudaEvent_t ev_fork, ev_join;
    cudaStreamCreateWithFlags(&s2, cudaStreamNonBlocking);
    cudaEventCreateWithFlags(&ev_fork, cudaEventDisableTiming);
    cudaEventCreateWithFlags(&ev_join, cudaEventDisableTiming);

    const int GRID_T = (N_NODES + MT - 1) / MT;   // 391

    // default stream: prep -> Z-gemm
    prep_kernel<<<256 + (N_NODES * D_OUT / 4 + 255) / 256, 256>>>(W0, W1);
    gemm_hmma_kernel<1><<<GRID_T, 256, HMMA_SMEM>>>(feat, b0, scale0, offset0, out);
    cudaEventRecord(ev_fork, 0);

    // fork: f0-gemm on s2, concurrent (tail-overlapping) with spmm+ln1
    cudaStreamWaitEvent(s2, ev_fork, 0);
    gemm_hmma_kernel<0><<<GRID_T, 256, HMMA_SMEM, s2>>>(feat, b0, scale0, offset0, out);
    cudaEventRecord(ev_join, s2);

    spmm_kernel<<<(N_EDGES / EPW + 7) / 8, 256>>>(erow, ecol, eval);
    ln1_kernel<<<(N_NODES + 7) / 8, 256>>>(b1, scale1, offset1, out);

    cudaStreamWaitEvent(0, ev_join, 0);
}